// round 1
// baseline (speedup 1.0000x reference)
#include <cuda_runtime.h>
#include <math.h>

#define NIMG 16
#define CCH 256
#define NPIX 4096            // 64*64
#define IMG_STRIDE (CCH*NPIX)

// ---- scratch (static device globals; no allocation) ----
__device__ float g_q[NIMG*CCH*NPIX];
__device__ float g_k[NIMG*CCH*NPIX];
__device__ float g_v[NIMG*CCH*NPIX];
__device__ float g_Qp[4194304];
__device__ float g_Kp[4194304];
__device__ float g_Vp[4194304];
__device__ float g_Val[4194304];
__device__ float g_S[2*2048*2048];
__device__ float g_part[1048576];
__device__ float g_att[NIMG*CCH*NPIX];
__device__ float g_xs1[NIMG*CCH*NPIX];
__device__ float g_ff[NIMG*CCH*NPIX];

// ===================== tiled SGEMM (NN), batched with strides =====================
// C[z][M,N] = A[z][M,K](lda) * B[z][K,N](ldb)
__global__ void __launch_bounds__(256) gemm_nn_kernel(
    const float* __restrict__ A, const float* __restrict__ B, float* __restrict__ Cm,
    int M, int N, int K, int lda, int ldb, int ldc,
    long sA, long sB, long sC)
{
    A  += (long)blockIdx.z * sA;
    B  += (long)blockIdx.z * sB;
    Cm += (long)blockIdx.z * sC;
    const int m0 = blockIdx.y * 64, n0 = blockIdx.x * 64;
    __shared__ __align__(16) float As[16][68];
    __shared__ __align__(16) float Bs[16][64];
    const int tid = threadIdx.x;
    const int tx = tid & 15, ty = tid >> 4;
    float acc[4][4] = {};
    for (int k0 = 0; k0 < K; k0 += 16) {
#pragma unroll
        for (int it = 0; it < 4; it++) {
            int id = tid + it * 256;
            int m = id >> 4, kk = id & 15;
            As[kk][m] = (m0 + m < M) ? A[(long)(m0 + m) * lda + k0 + kk] : 0.f;
        }
#pragma unroll
        for (int it = 0; it < 4; it++) {
            int id = tid + it * 256;
            int kk = id >> 6, nn = id & 63;
            Bs[kk][nn] = (n0 + nn < N) ? B[(long)(k0 + kk) * ldb + n0 + nn] : 0.f;
        }
        __syncthreads();
#pragma unroll
        for (int kk = 0; kk < 16; kk++) {
            float4 a4 = *(const float4*)&As[kk][ty * 4];
            float4 b4 = *(const float4*)&Bs[kk][tx * 4];
            float ar[4] = {a4.x, a4.y, a4.z, a4.w};
            float br[4] = {b4.x, b4.y, b4.z, b4.w};
#pragma unroll
            for (int i = 0; i < 4; i++)
#pragma unroll
                for (int j = 0; j < 4; j++)
                    acc[i][j] += ar[i] * br[j];
        }
        __syncthreads();
    }
#pragma unroll
    for (int i = 0; i < 4; i++) {
        int m = m0 + ty * 4 + i;
        if (m >= M) continue;
#pragma unroll
        for (int j = 0; j < 4; j++) {
            int nn = n0 + tx * 4 + j;
            if (nn < N) Cm[(long)m * ldc + nn] = acc[i][j];
        }
    }
}

// ===================== tiled SGEMM (NT) with deterministic split-K ================
// contiguous operands: A[batch][M,K], B[batch][N,K], C[z][M,N], z = batch*splitk+ks
__global__ void __launch_bounds__(256) gemm_nt_kernel(
    const float* __restrict__ A, const float* __restrict__ B, float* __restrict__ Cm,
    int M, int N, int K, int splitk)
{
    const int z = blockIdx.z;
    const int batch = z / splitk, ks = z - batch * splitk;
    A  += (long)batch * M * K;
    B  += (long)batch * N * K;
    Cm += (long)z * M * N;
    const int kchunk = K / splitk;
    const int kbeg = ks * kchunk;
    const int m0 = blockIdx.y * 64, n0 = blockIdx.x * 64;
    __shared__ __align__(16) float As[16][68];
    __shared__ __align__(16) float Bs[16][68];
    const int tid = threadIdx.x;
    const int tx = tid & 15, ty = tid >> 4;
    float acc[4][4] = {};
    for (int k0 = kbeg; k0 < kbeg + kchunk; k0 += 16) {
#pragma unroll
        for (int it = 0; it < 4; it++) {
            int id = tid + it * 256;
            int m = id >> 4, kk = id & 15;
            As[kk][m] = (m0 + m < M) ? A[(long)(m0 + m) * K + k0 + kk] : 0.f;
        }
#pragma unroll
        for (int it = 0; it < 4; it++) {
            int id = tid + it * 256;
            int nn = id >> 4, kk = id & 15;
            Bs[kk][nn] = (n0 + nn < N) ? B[(long)(n0 + nn) * K + k0 + kk] : 0.f;
        }
        __syncthreads();
#pragma unroll
        for (int kk = 0; kk < 16; kk++) {
            float4 a4 = *(const float4*)&As[kk][ty * 4];
            float4 b4 = *(const float4*)&Bs[kk][tx * 4];
            float ar[4] = {a4.x, a4.y, a4.z, a4.w};
            float br[4] = {b4.x, b4.y, b4.z, b4.w};
#pragma unroll
            for (int i = 0; i < 4; i++)
#pragma unroll
                for (int j = 0; j < 4; j++)
                    acc[i][j] += ar[i] * br[j];
        }
        __syncthreads();
    }
#pragma unroll
    for (int i = 0; i < 4; i++) {
        int m = m0 + ty * 4 + i;
        if (m >= M) continue;
#pragma unroll
        for (int j = 0; j < 4; j++) {
            int nn = n0 + tx * 4 + j;
            if (nn < N) Cm[(long)m * N + nn] = acc[i][j];
        }
    }
}

__global__ void reduce_splitk_kernel(const float* __restrict__ part, float* __restrict__ S,
                                     int per, int splitk)
{
    long idx = (long)blockIdx.x * 256 + threadIdx.x;  // over 2*per
    int b = (int)(idx / per);
    int r = (int)(idx - (long)b * per);
    float s = 0.f;
    for (int ks = 0; ks < splitk; ks++)
        s += part[(long)(b * splitk + ks) * per + r];
    S[idx] = s;
}

// ===================== patchify / unpatchify ======================================
// token n = (t, ohi, owi); feature d = (c, pi, pj)
__global__ void patchify_kernel(const float* __restrict__ src, const float* __restrict__ bias,
                                float* __restrict__ dst, int P, int c0)
{
    const int o = 64 / P;
    const int d = 64 * P * P;
    const long npbd = (long)(8 * o * o) * d;   // 2097152
    long idx = (long)blockIdx.x * 256 + threadIdx.x;
    int b = (int)(idx / npbd);
    long rem = idx - (long)b * npbd;
    int nn = (int)(rem / d);
    int dd = (int)(rem - (long)nn * d);
    int t = nn / (o * o); int r = nn - t * o * o; int ohi = r / o; int owi = r - ohi * o;
    int cc = dd / (P * P); int rr = dd - cc * P * P; int pi = rr / P; int pj = rr - pi * P;
    long si = ((((long)(b * 8 + t) * CCH) + c0 + cc) * 64 + ohi * P + pi) * 64 + owi * P + pj;
    dst[idx] = src[si] + bias[c0 + cc];
}

__global__ void unpatchify_kernel(const float* __restrict__ val, float* __restrict__ dst,
                                  int P, int c0)
{
    const int o = 64 / P;
    const int d = 64 * P * P;
    const long npbd = (long)(8 * o * o) * d;
    long idx = (long)blockIdx.x * 256 + threadIdx.x;
    int b = (int)(idx / npbd);
    long rem = idx - (long)b * npbd;
    int nn = (int)(rem / d);
    int dd = (int)(rem - (long)nn * d);
    int t = nn / (o * o); int r = nn - t * o * o; int ohi = r / o; int owi = r - ohi * o;
    int cc = dd / (P * P); int rr = dd - cc * P * P; int pi = rr / P; int pj = rr - pi * P;
    long si = ((((long)(b * 8 + t) * CCH) + c0 + cc) * 64 + ohi * P + pi) * 64 + owi * P + pj;
    dst[si] = val[idx];
}

// ===================== softmax (row-wise, scale folded in) ========================
__global__ void softmax_kernel(float* __restrict__ S, int n, float scale)
{
    __shared__ float buf[2048];
    __shared__ float red[256];
    const long row = blockIdx.x;
    float* p = S + row * (long)n;
    const int tid = threadIdx.x;
    float m = -1e30f;
    for (int i = tid; i < n; i += 256) { float v = p[i] * scale; buf[i] = v; m = fmaxf(m, v); }
    red[tid] = m; __syncthreads();
    for (int s = 128; s > 0; s >>= 1) { if (tid < s) red[tid] = fmaxf(red[tid], red[tid + s]); __syncthreads(); }
    m = red[0]; __syncthreads();
    float sum = 0.f;
    for (int i = tid; i < n; i += 256) { float e = expf(buf[i] - m); buf[i] = e; sum += e; }
    red[tid] = sum; __syncthreads();
    for (int s = 128; s > 0; s >>= 1) { if (tid < s) red[tid] += red[tid + s]; __syncthreads(); }
    float inv = 1.f / red[0];
    for (int i = tid; i < n; i += 256) p[i] = buf[i] * inv;
}

// ===================== conv3x3 implicit GEMM (fused bias+leaky+residual) ==========
// block: 64 output channels x one image row (64 px); loop over 256 input channels
__global__ void __launch_bounds__(256) conv3x3_kernel(
    const float* __restrict__ in, const float* __restrict__ Wt,
    const float* __restrict__ bias, const float* __restrict__ res,
    float* __restrict__ out, int dil, int addres)
{
    const int ocb = blockIdx.x, y = blockIdx.y, img = blockIdx.z;
    const int tid = threadIdx.x;
    const int tx = tid & 15, ty = tid >> 4;
    __shared__ float shx[3][72];
    __shared__ float shw[64][9];
    float acc[4][4] = {};
    const int W2 = 64 + 2 * dil;
    const int oc0 = ocb * 64;
    for (int c = 0; c < 256; c++) {
        for (int idx = tid; idx < 3 * W2; idx += 256) {
            int r = idx / W2, xx = idx - r * W2;
            int gy = y + (r - 1) * dil, gx = xx - dil;
            float v = 0.f;
            if ((unsigned)gy < 64u && (unsigned)gx < 64u)
                v = in[(((long)img * 256 + c) * 64 + gy) * 64 + gx];
            shx[r][xx] = v;
        }
        if (tid < 64) {
            int oo = tid;
#pragma unroll
            for (int tap = 0; tap < 9; tap++)
                shw[oo][tap] = Wt[((long)(oc0 + oo) * 256 + c) * 9 + tap];
        }
        __syncthreads();
#pragma unroll
        for (int ky = 0; ky < 3; ky++) {
#pragma unroll
            for (int kx = 0; kx < 3; kx++) {
                const int tap = ky * 3 + kx;
                float wv[4], xv[4];
#pragma unroll
                for (int i = 0; i < 4; i++) wv[i] = shw[ty * 4 + i][tap];
                const int xb = tx * 4 + kx * dil;
#pragma unroll
                for (int j = 0; j < 4; j++) xv[j] = shx[ky][xb + j];
#pragma unroll
                for (int i = 0; i < 4; i++)
#pragma unroll
                    for (int j = 0; j < 4; j++)
                        acc[i][j] += wv[i] * xv[j];
            }
        }
        __syncthreads();
    }
#pragma unroll
    for (int i = 0; i < 4; i++) {
        const int oc = oc0 + ty * 4 + i;
        const float bv = bias[oc];
#pragma unroll
        for (int j = 0; j < 4; j++) {
            const int x = tx * 4 + j;
            float v = acc[i][j] + bv;
            v = (v > 0.f) ? v : 0.2f * v;
            long oi = (((long)img * 256 + oc) * 64 + y) * 64 + x;
            if (addres) v += res[oi];
            out[oi] = v;
        }
    }
}

// ===================== launcher ===================================================
extern "C" void kernel_launch(void* const* d_in, const int* in_sizes, int n_in,
                              void* d_out, int out_size)
{
    const float* xs  = (const float*)d_in[0];
    // d_in[1] = ms : dead in reference (masked_fill bug), unused
    const float* Wq  = (const float*)d_in[2];
    const float* bq  = (const float*)d_in[3];
    const float* Wk  = (const float*)d_in[4];
    const float* bk  = (const float*)d_in[5];
    const float* Wv  = (const float*)d_in[6];
    const float* bv  = (const float*)d_in[7];
    const float* Wl  = (const float*)d_in[8];
    const float* bl  = (const float*)d_in[9];
    const float* Wf1 = (const float*)d_in[10];
    const float* bf1 = (const float*)d_in[11];
    const float* Wf2 = (const float*)d_in[12];
    const float* bf2 = (const float*)d_in[13];
    float* out = (float*)d_out;

    float *gq, *gk, *gv, *gQp, *gKp, *gVp, *gVal, *gS, *gPart, *gAtt, *gXs1, *gFf;
    cudaGetSymbolAddress((void**)&gq,   g_q);
    cudaGetSymbolAddress((void**)&gk,   g_k);
    cudaGetSymbolAddress((void**)&gv,   g_v);
    cudaGetSymbolAddress((void**)&gQp,  g_Qp);
    cudaGetSymbolAddress((void**)&gKp,  g_Kp);
    cudaGetSymbolAddress((void**)&gVp,  g_Vp);
    cudaGetSymbolAddress((void**)&gVal, g_Val);
    cudaGetSymbolAddress((void**)&gS,   g_S);
    cudaGetSymbolAddress((void**)&gPart,g_part);
    cudaGetSymbolAddress((void**)&gAtt, g_att);
    cudaGetSymbolAddress((void**)&gXs1, g_xs1);
    cudaGetSymbolAddress((void**)&gFf,  g_ff);

    dim3 blk(256);

    // QKV projections: C[img][o][p] = W[o][c] * xs[img][c][p]
    dim3 gproj(NPIX / 64, CCH / 64, NIMG);
    gemm_nn_kernel<<<gproj, blk>>>(Wq, xs, gq, CCH, NPIX, CCH, CCH, NPIX, NPIX,
                                   0L, (long)IMG_STRIDE, (long)IMG_STRIDE);
    gemm_nn_kernel<<<gproj, blk>>>(Wk, xs, gk, CCH, NPIX, CCH, CCH, NPIX, NPIX,
                                   0L, (long)IMG_STRIDE, (long)IMG_STRIDE);
    gemm_nn_kernel<<<gproj, blk>>>(Wv, xs, gv, CCH, NPIX, CCH, CCH, NPIX, NPIX,
                                   0L, (long)IMG_STRIDE, (long)IMG_STRIDE);

    const int PS[4]     = {32, 16, 8, 4};
    const int SPLITK[4] = {64, 16, 2, 1};
    for (int s = 0; s < 4; s++) {
        const int P = PS[s], o = 64 / P, n = 8 * o * o, d = 64 * P * P, c0 = s * 64;
        const int splitk = SPLITK[s];
        const int total = 2 * n * d;              // 4194304 always
        patchify_kernel<<<total / 256, blk>>>(gq, bq, gQp, P, c0);
        patchify_kernel<<<total / 256, blk>>>(gk, bk, gKp, P, c0);
        patchify_kernel<<<total / 256, blk>>>(gv, bv, gVp, P, c0);

        float* Cdst = (splitk > 1) ? gPart : gS;
        dim3 gsc((n + 63) / 64, (n + 63) / 64, 2 * splitk);
        gemm_nt_kernel<<<gsc, blk>>>(gQp, gKp, Cdst, n, n, d, splitk);
        if (splitk > 1)
            reduce_splitk_kernel<<<(2 * n * n) / 256, blk>>>(gPart, gS, n * n, splitk);

        softmax_kernel<<<2 * n, blk>>>(gS, n, 1.0f / sqrtf((float)d));

        dim3 gav((d + 63) / 64, (n + 63) / 64, 2);
        gemm_nn_kernel<<<gav, blk>>>(gS, gVp, gVal, n, d, n, n, d, d,
                                     (long)n * n, (long)n * d, (long)n * d);
        unpatchify_kernel<<<total / 256, blk>>>(gVal, gAtt, P, c0);
    }

    // xs1 = xs + leaky(conv3x3(att, Wl) + bl)
    dim3 gconv(4, 64, NIMG);
    conv3x3_kernel<<<gconv, blk>>>(gAtt, Wl, bl, xs, gXs1, 1, 1);
    // ff = leaky(conv3x3(xs1, Wf1) + bf1)
    conv3x3_kernel<<<gconv, blk>>>(gXs1, Wf1, bf1, nullptr, gFf, 1, 0);
    // out = xs1 + leaky(conv3x3_dil2(ff, Wf2) + bf2)
    conv3x3_kernel<<<gconv, blk>>>(gFf, Wf2, bf2, gXs1, out, 2, 1);
}

// round 3
// speedup vs baseline: 3.8346x; 3.8346x over previous
#include <cuda_runtime.h>
#include <math.h>
#include <stdint.h>

#define NIMG 16
#define CCH 256
#define NPIX 4096            // 64*64

// ---- scratch (static device globals; no allocation) ----
__device__ float g_q[NIMG*CCH*NPIX];
__device__ float g_k[NIMG*CCH*NPIX];
__device__ float g_v[NIMG*CCH*NPIX];
__device__ float g_Qp[4194304];
__device__ float g_Kp[4194304];
__device__ float g_Vp[4194304];
__device__ float g_Val[4194304];
__device__ float g_S[2*2048*2048];
__device__ float g_part[1048576];
__device__ float g_att[NIMG*CCH*NPIX];
__device__ float g_xs1[NIMG*CCH*NPIX];
__device__ float g_ff[NIMG*CCH*NPIX];

// ============================================================================
// mma.sync tf32 helpers (arch-neutral PTX, works on plain sm_103 target)
// ============================================================================
__device__ __forceinline__ uint32_t f2tf(float x) {
    uint32_t u;
    asm("cvt.rna.tf32.f32 %0, %1;" : "=r"(u) : "f"(x));
    return u;
}

__device__ __forceinline__ void mma8(float* d, const uint32_t* a, const uint32_t* b) {
    asm volatile(
        "mma.sync.aligned.m16n8k8.row.col.f32.tf32.tf32.f32 "
        "{%0,%1,%2,%3}, {%4,%5,%6,%7}, {%8,%9}, {%0,%1,%2,%3};"
        : "+f"(d[0]), "+f"(d[1]), "+f"(d[2]), "+f"(d[3])
        : "r"(a[0]), "r"(a[1]), "r"(a[2]), "r"(a[3]), "r"(b[0]), "r"(b[1]));
}

// ============================================================================
// mma conv / 1x1-projection kernel (implicit im2col)
//   out[oc][pix] = act(sum_{c,tap} W[oc][c*ks*ks+tap] * in_shift[c,tap][pix] + bias) (+res)
//   tile: M=128 oc x N=128 pixels; 8 warps = 2(M) x 4(N); K-chunk 32
// ============================================================================
__global__ void __launch_bounds__(256) mma_conv_kernel(
    const float* __restrict__ in, const float* __restrict__ Wt,
    const float* __restrict__ bias, const float* __restrict__ res,
    float* __restrict__ out, int ks, int dil, int do_leaky, int addres)
{
    __shared__ uint32_t As[128][36];
    __shared__ uint32_t Bs[128][36];
    const int tid = threadIdx.x;
    const int lane = tid & 31, wid = tid >> 5;
    const int wm = wid & 1, wn = wid >> 1;
    const int K = CCH * ks * ks;
    const int img = blockIdx.x >> 5;
    const int p0 = (blockIdx.x & 31) * 128;
    const int m0 = blockIdx.y * 128;
    const float* inimg = in + (long)img * CCH * NPIX;

    const int wr  = tid >> 1;          // row within tile (0..127)
    const int wkh = (tid & 1) * 16;    // k half
    const int py = (p0 + wr) >> 6, px = (p0 + wr) & 63;

    float acc[4][4][4] = {};

    for (int k0 = 0; k0 < K; k0 += 32) {
        __syncthreads();
        // A: weights [m][k]
        {
            const float* src = Wt + (long)(m0 + wr) * K + k0 + wkh;
#pragma unroll
            for (int i = 0; i < 4; i++) {
                float4 v = *(const float4*)(src + i * 4);
                As[wr][wkh + i*4 + 0] = f2tf(v.x);
                As[wr][wkh + i*4 + 1] = f2tf(v.y);
                As[wr][wkh + i*4 + 2] = f2tf(v.z);
                As[wr][wkh + i*4 + 3] = f2tf(v.w);
            }
        }
        // B: implicit im2col [n][k]
        if (ks == 1) {
#pragma unroll
            for (int i = 0; i < 16; i++) {
                int kk = wkh + i;
                float v = inimg[(k0 + kk) * NPIX + p0 + wr];
                Bs[wr][kk] = f2tf(v);
            }
        } else {
#pragma unroll
            for (int i = 0; i < 16; i++) {
                int k = k0 + wkh + i;
                int c = k / 9;
                int tap = k - c * 9;
                int ky = tap / 3, kx = tap - ky * 3;
                int sy = py + (ky - 1) * dil;
                int sx = px + (kx - 1) * dil;
                float v = 0.f;
                if ((unsigned)sy < 64u && (unsigned)sx < 64u)
                    v = inimg[(c << 12) + (sy << 6) + sx];
                Bs[wr][wkh + i] = f2tf(v);
            }
        }
        __syncthreads();
#pragma unroll
        for (int s8 = 0; s8 < 4; s8++) {
            const int ac = s8 * 8 + (lane & 3);
            const int ar = wm * 64 + (lane >> 2);
            const int bn = wn * 32 + (lane >> 2);
            uint32_t a[4][4], b[4][2];
#pragma unroll
            for (int mi = 0; mi < 4; mi++) {
                a[mi][0] = As[ar + mi*16    ][ac];
                a[mi][1] = As[ar + mi*16 + 8][ac];
                a[mi][2] = As[ar + mi*16    ][ac + 4];
                a[mi][3] = As[ar + mi*16 + 8][ac + 4];
            }
#pragma unroll
            for (int ni = 0; ni < 4; ni++) {
                b[ni][0] = Bs[bn + ni*8][ac];
                b[ni][1] = Bs[bn + ni*8][ac + 4];
            }
#pragma unroll
            for (int mi = 0; mi < 4; mi++)
#pragma unroll
                for (int ni = 0; ni < 4; ni++)
                    mma8(acc[mi][ni], a[mi], b[ni]);
        }
    }

    // epilogue: bias + leaky + residual
    const int orow = m0 + wm * 64 + (lane >> 2);
    const int ocol = p0 + wn * 32 + (lane & 3) * 2;
#pragma unroll
    for (int mi = 0; mi < 4; mi++) {
        const int oca = orow + mi * 16;
        const int ocb = oca + 8;
        const float ba = bias[oca], bb = bias[ocb];
#pragma unroll
        for (int ni = 0; ni < 4; ni++) {
            const int n = ocol + ni * 8;
            long ia = ((long)img * 256 + oca) * NPIX + n;
            long ib = ((long)img * 256 + ocb) * NPIX + n;
            float v0 = acc[mi][ni][0] + ba, v1 = acc[mi][ni][1] + ba;
            float v2 = acc[mi][ni][2] + bb, v3 = acc[mi][ni][3] + bb;
            if (do_leaky) {
                v0 = (v0 > 0.f) ? v0 : 0.2f * v0;
                v1 = (v1 > 0.f) ? v1 : 0.2f * v1;
                v2 = (v2 > 0.f) ? v2 : 0.2f * v2;
                v3 = (v3 > 0.f) ? v3 : 0.2f * v3;
            }
            if (addres) {
                v0 += res[ia]; v1 += res[ia + 1];
                v2 += res[ib]; v3 += res[ib + 1];
            }
            out[ia] = v0; out[ia + 1] = v1;
            out[ib] = v2; out[ib + 1] = v3;
        }
    }
}

// ============================================================================
// mma NT GEMM: C[z][m][n] = sum_k A[z][m*K+k] * B[z][n*K+k]   (M,N mult of 128)
// ============================================================================
__global__ void __launch_bounds__(256) mma_nt_kernel(
    const float* __restrict__ A, const float* __restrict__ B, float* __restrict__ C,
    int N, int K, long sA, long sB, long sC)
{
    __shared__ uint32_t As[128][36];
    __shared__ uint32_t Bs[128][36];
    const int tid = threadIdx.x;
    const int lane = tid & 31, wid = tid >> 5;
    const int wm = wid & 1, wn = wid >> 1;
    const int n0 = blockIdx.x * 128, m0 = blockIdx.y * 128;
    A += (long)blockIdx.z * sA;
    B += (long)blockIdx.z * sB;
    C += (long)blockIdx.z * sC;

    const int wr = tid >> 1;
    const int wkh = (tid & 1) * 16;

    float acc[4][4][4] = {};
    for (int k0 = 0; k0 < K; k0 += 32) {
        __syncthreads();
        {
            const float* sa = A + (long)(m0 + wr) * K + k0 + wkh;
            const float* sb = B + (long)(n0 + wr) * K + k0 + wkh;
#pragma unroll
            for (int i = 0; i < 4; i++) {
                float4 va = *(const float4*)(sa + i * 4);
                float4 vb = *(const float4*)(sb + i * 4);
                As[wr][wkh + i*4 + 0] = f2tf(va.x);
                As[wr][wkh + i*4 + 1] = f2tf(va.y);
                As[wr][wkh + i*4 + 2] = f2tf(va.z);
                As[wr][wkh + i*4 + 3] = f2tf(va.w);
                Bs[wr][wkh + i*4 + 0] = f2tf(vb.x);
                Bs[wr][wkh + i*4 + 1] = f2tf(vb.y);
                Bs[wr][wkh + i*4 + 2] = f2tf(vb.z);
                Bs[wr][wkh + i*4 + 3] = f2tf(vb.w);
            }
        }
        __syncthreads();
#pragma unroll
        for (int s8 = 0; s8 < 4; s8++) {
            const int ac = s8 * 8 + (lane & 3);
            const int ar = wm * 64 + (lane >> 2);
            const int bn = wn * 32 + (lane >> 2);
            uint32_t a[4][4], b[4][2];
#pragma unroll
            for (int mi = 0; mi < 4; mi++) {
                a[mi][0] = As[ar + mi*16    ][ac];
                a[mi][1] = As[ar + mi*16 + 8][ac];
                a[mi][2] = As[ar + mi*16    ][ac + 4];
                a[mi][3] = As[ar + mi*16 + 8][ac + 4];
            }
#pragma unroll
            for (int ni = 0; ni < 4; ni++) {
                b[ni][0] = Bs[bn + ni*8][ac];
                b[ni][1] = Bs[bn + ni*8][ac + 4];
            }
#pragma unroll
            for (int mi = 0; mi < 4; mi++)
#pragma unroll
                for (int ni = 0; ni < 4; ni++)
                    mma8(acc[mi][ni], a[mi], b[ni]);
        }
    }
    const int orow = m0 + wm * 64 + (lane >> 2);
    const int ocol = n0 + wn * 32 + (lane & 3) * 2;
#pragma unroll
    for (int mi = 0; mi < 4; mi++) {
        long ra = (long)(orow + mi * 16) * N;
        long rb = (long)(orow + mi * 16 + 8) * N;
#pragma unroll
        for (int ni = 0; ni < 4; ni++) {
            int n = ocol + ni * 8;
            C[ra + n] = acc[mi][ni][0]; C[ra + n + 1] = acc[mi][ni][1];
            C[rb + n] = acc[mi][ni][2]; C[rb + n + 1] = acc[mi][ni][3];
        }
    }
}

// ============================================================================
// mma NN GEMM: C[z][m][n] = sum_k A[z][m*K+k] * B[z][k*N+n]
// ============================================================================
__global__ void __launch_bounds__(256) mma_nn_kernel(
    const float* __restrict__ A, const float* __restrict__ B, float* __restrict__ C,
    int N, int K, long sA, long sB, long sC)
{
    __shared__ uint32_t As[128][36];
    __shared__ uint32_t Bs[32][132];
    const int tid = threadIdx.x;
    const int lane = tid & 31, wid = tid >> 5;
    const int wm = wid & 1, wn = wid >> 1;
    const int n0 = blockIdx.x * 128, m0 = blockIdx.y * 128;
    A += (long)blockIdx.z * sA;
    B += (long)blockIdx.z * sB;
    C += (long)blockIdx.z * sC;

    const int wr = tid >> 1;
    const int wkh = (tid & 1) * 16;
    const int bk = tid >> 3;            // 0..31
    const int bn = (tid & 7) * 16;      // 0..112

    float acc[4][4][4] = {};
    for (int k0 = 0; k0 < K; k0 += 32) {
        __syncthreads();
        {
            const float* sa = A + (long)(m0 + wr) * K + k0 + wkh;
#pragma unroll
            for (int i = 0; i < 4; i++) {
                float4 va = *(const float4*)(sa + i * 4);
                As[wr][wkh + i*4 + 0] = f2tf(va.x);
                As[wr][wkh + i*4 + 1] = f2tf(va.y);
                As[wr][wkh + i*4 + 2] = f2tf(va.z);
                As[wr][wkh + i*4 + 3] = f2tf(va.w);
            }
            const float* sb = B + (long)(k0 + bk) * N + n0 + bn;
#pragma unroll
            for (int i = 0; i < 4; i++) {
                float4 vb = *(const float4*)(sb + i * 4);
                Bs[bk][bn + i*4 + 0] = f2tf(vb.x);
                Bs[bk][bn + i*4 + 1] = f2tf(vb.y);
                Bs[bk][bn + i*4 + 2] = f2tf(vb.z);
                Bs[bk][bn + i*4 + 3] = f2tf(vb.w);
            }
        }
        __syncthreads();
#pragma unroll
        for (int s8 = 0; s8 < 4; s8++) {
            const int ac = s8 * 8 + (lane & 3);
            const int ar = wm * 64 + (lane >> 2);
            const int bc = wn * 32 + (lane >> 2);
            uint32_t a[4][4], b[4][2];
#pragma unroll
            for (int mi = 0; mi < 4; mi++) {
                a[mi][0] = As[ar + mi*16    ][ac];
                a[mi][1] = As[ar + mi*16 + 8][ac];
                a[mi][2] = As[ar + mi*16    ][ac + 4];
                a[mi][3] = As[ar + mi*16 + 8][ac + 4];
            }
#pragma unroll
            for (int ni = 0; ni < 4; ni++) {
                b[ni][0] = Bs[ac    ][bc + ni*8];
                b[ni][1] = Bs[ac + 4][bc + ni*8];
            }
#pragma unroll
            for (int mi = 0; mi < 4; mi++)
#pragma unroll
                for (int ni = 0; ni < 4; ni++)
                    mma8(acc[mi][ni], a[mi], b[ni]);
        }
    }
    const int orow = m0 + wm * 64 + (lane >> 2);
    const int ocol = n0 + wn * 32 + (lane & 3) * 2;
#pragma unroll
    for (int mi = 0; mi < 4; mi++) {
        long ra = (long)(orow + mi * 16) * N;
        long rb = (long)(orow + mi * 16 + 8) * N;
#pragma unroll
        for (int ni = 0; ni < 4; ni++) {
            int n = ocol + ni * 8;
            C[ra + n] = acc[mi][ni][0]; C[ra + n + 1] = acc[mi][ni][1];
            C[rb + n] = acc[mi][ni][2]; C[rb + n + 1] = acc[mi][ni][3];
        }
    }
}

// ===================== SIMT SGEMM (NN), batched with strides ======================
__global__ void __launch_bounds__(256) gemm_nn_kernel(
    const float* __restrict__ A, const float* __restrict__ B, float* __restrict__ Cm,
    int M, int N, int K, int lda, int ldb, int ldc,
    long sA, long sB, long sC)
{
    A  += (long)blockIdx.z * sA;
    B  += (long)blockIdx.z * sB;
    Cm += (long)blockIdx.z * sC;
    const int m0 = blockIdx.y * 64, n0 = blockIdx.x * 64;
    __shared__ __align__(16) float As[16][68];
    __shared__ __align__(16) float Bs[16][64];
    const int tid = threadIdx.x;
    const int tx = tid & 15, ty = tid >> 4;
    float acc[4][4] = {};
    for (int k0 = 0; k0 < K; k0 += 16) {
#pragma unroll
        for (int it = 0; it < 4; it++) {
            int id = tid + it * 256;
            int m = id >> 4, kk = id & 15;
            As[kk][m] = (m0 + m < M) ? A[(long)(m0 + m) * lda + k0 + kk] : 0.f;
        }
#pragma unroll
        for (int it = 0; it < 4; it++) {
            int id = tid + it * 256;
            int kk = id >> 6, nn = id & 63;
            Bs[kk][nn] = (n0 + nn < N) ? B[(long)(k0 + kk) * ldb + n0 + nn] : 0.f;
        }
        __syncthreads();
#pragma unroll
        for (int kk = 0; kk < 16; kk++) {
            float4 a4 = *(const float4*)&As[kk][ty * 4];
            float4 b4 = *(const float4*)&Bs[kk][tx * 4];
            float ar[4] = {a4.x, a4.y, a4.z, a4.w};
            float br[4] = {b4.x, b4.y, b4.z, b4.w};
#pragma unroll
            for (int i = 0; i < 4; i++)
#pragma unroll
                for (int j = 0; j < 4; j++)
                    acc[i][j] += ar[i] * br[j];
        }
        __syncthreads();
    }
#pragma unroll
    for (int i = 0; i < 4; i++) {
        int m = m0 + ty * 4 + i;
        if (m >= M) continue;
#pragma unroll
        for (int j = 0; j < 4; j++) {
            int nn = n0 + tx * 4 + j;
            if (nn < N) Cm[(long)m * ldc + nn] = acc[i][j];
        }
    }
}

// ===================== SIMT SGEMM (NT), deterministic split-K =====================
__global__ void __launch_bounds__(256) gemm_nt_kernel(
    const float* __restrict__ A, const float* __restrict__ B, float* __restrict__ Cm,
    int M, int N, int K, int splitk)
{
    const int z = blockIdx.z;
    const int batch = z / splitk, ks = z - batch * splitk;
    A  += (long)batch * M * K;
    B  += (long)batch * N * K;
    Cm += (long)z * M * N;
    const int kchunk = K / splitk;
    const int kbeg = ks * kchunk;
    const int m0 = blockIdx.y * 64, n0 = blockIdx.x * 64;
    __shared__ __align__(16) float As[16][68];
    __shared__ __align__(16) float Bs[16][68];
    const int tid = threadIdx.x;
    const int tx = tid & 15, ty = tid >> 4;
    float acc[4][4] = {};
    for (int k0 = kbeg; k0 < kbeg + kchunk; k0 += 16) {
#pragma unroll
        for (int it = 0; it < 4; it++) {
            int id = tid + it * 256;
            int m = id >> 4, kk = id & 15;
            As[kk][m] = (m0 + m < M) ? A[(long)(m0 + m) * K + k0 + kk] : 0.f;
        }
#pragma unroll
        for (int it = 0; it < 4; it++) {
            int id = tid + it * 256;
            int nn = id >> 4, kk = id & 15;
            Bs[kk][nn] = (n0 + nn < N) ? B[(long)(n0 + nn) * K + k0 + kk] : 0.f;
        }
        __syncthreads();
#pragma unroll
        for (int kk = 0; kk < 16; kk++) {
            float4 a4 = *(const float4*)&As[kk][ty * 4];
            float4 b4 = *(const float4*)&Bs[kk][tx * 4];
            float ar[4] = {a4.x, a4.y, a4.z, a4.w};
            float br[4] = {b4.x, b4.y, b4.z, b4.w};
#pragma unroll
            for (int i = 0; i < 4; i++)
#pragma unroll
                for (int j = 0; j < 4; j++)
                    acc[i][j] += ar[i] * br[j];
        }
        __syncthreads();
    }
#pragma unroll
    for (int i = 0; i < 4; i++) {
        int m = m0 + ty * 4 + i;
        if (m >= M) continue;
#pragma unroll
        for (int j = 0; j < 4; j++) {
            int nn = n0 + tx * 4 + j;
            if (nn < N) Cm[(long)m * N + nn] = acc[i][j];
        }
    }
}

__global__ void reduce_splitk_kernel(const float* __restrict__ part, float* __restrict__ S,
                                     int per, int splitk)
{
    long idx = (long)blockIdx.x * 256 + threadIdx.x;
    int b = (int)(idx / per);
    int r = (int)(idx - (long)b * per);
    float s = 0.f;
    for (int ks = 0; ks < splitk; ks++)
        s += part[(long)(b * splitk + ks) * per + r];
    S[idx] = s;
}

// ===================== patchify / unpatchify ======================================
__global__ void patchify_kernel(const float* __restrict__ src,
                                float* __restrict__ dst, int P, int c0)
{
    const int o = 64 / P;
    const int d = 64 * P * P;
    const long npbd = (long)(8 * o * o) * d;
    long idx = (long)blockIdx.x * 256 + threadIdx.x;
    int b = (int)(idx / npbd);
    long rem = idx - (long)b * npbd;
    int nn = (int)(rem / d);
    int dd = (int)(rem - (long)nn * d);
    int t = nn / (o * o); int r = nn - t * o * o; int ohi = r / o; int owi = r - ohi * o;
    int cc = dd / (P * P); int rr = dd - cc * P * P; int pi = rr / P; int pj = rr - pi * P;
    long si = ((((long)(b * 8 + t) * CCH) + c0 + cc) * 64 + ohi * P + pi) * 64 + owi * P + pj;
    dst[idx] = src[si];
}

__global__ void unpatchify_kernel(const float* __restrict__ val, float* __restrict__ dst,
                                  int P, int c0)
{
    const int o = 64 / P;
    const int d = 64 * P * P;
    const long npbd = (long)(8 * o * o) * d;
    long idx = (long)blockIdx.x * 256 + threadIdx.x;
    int b = (int)(idx / npbd);
    long rem = idx - (long)b * npbd;
    int nn = (int)(rem / d);
    int dd = (int)(rem - (long)nn * d);
    int t = nn / (o * o); int r = nn - t * o * o; int ohi = r / o; int owi = r - ohi * o;
    int cc = dd / (P * P); int rr = dd - cc * P * P; int pi = rr / P; int pj = rr - pi * P;
    long si = ((((long)(b * 8 + t) * CCH) + c0 + cc) * 64 + ohi * P + pi) * 64 + owi * P + pj;
    dst[si] = val[idx];
}

// ===================== softmax (row-wise, scale folded in) ========================
__global__ void softmax_kernel(float* __restrict__ S, int n, float scale)
{
    __shared__ float buf[2048];
    __shared__ float red[256];
    const long row = blockIdx.x;
    float* p = S + row * (long)n;
    const int tid = threadIdx.x;
    float m = -1e30f;
    for (int i = tid; i < n; i += 256) { float v = p[i] * scale; buf[i] = v; m = fmaxf(m, v); }
    red[tid] = m; __syncthreads();
    for (int s = 128; s > 0; s >>= 1) { if (tid < s) red[tid] = fmaxf(red[tid], red[tid + s]); __syncthreads(); }
    m = red[0]; __syncthreads();
    float sum = 0.f;
    for (int i = tid; i < n; i += 256) { float e = expf(buf[i] - m); buf[i] = e; sum += e; }
    red[tid] = sum; __syncthreads();
    for (int s = 128; s > 0; s >>= 1) { if (tid < s) red[tid] += red[tid + s]; __syncthreads(); }
    float inv = 1.f / red[0];
    for (int i = tid; i < n; i += 256) p[i] = buf[i] * inv;
}

// ===================== launcher ===================================================
extern "C" void kernel_launch(void* const* d_in, const int* in_sizes, int n_in,
                              void* d_out, int out_size)
{
    const float* xs  = (const float*)d_in[0];
    const float* Wq  = (const float*)d_in[2];
    const float* bq  = (const float*)d_in[3];
    const float* Wk  = (const float*)d_in[4];
    const float* bk  = (const float*)d_in[5];
    const float* Wv  = (const float*)d_in[6];
    const float* bv  = (const float*)d_in[7];
    const float* Wl  = (const float*)d_in[8];
    const float* bl  = (const float*)d_in[9];
    const float* Wf1 = (const float*)d_in[10];
    const float* bf1 = (const float*)d_in[11];
    const float* Wf2 = (const float*)d_in[12];
    const float* bf2 = (const float*)d_in[13];
    float* out = (float*)d_out;

    float *gq, *gk, *gv, *gQp, *gKp, *gVp, *gVal, *gS, *gPart, *gAtt, *gXs1, *gFf;
    cudaGetSymbolAddress((void**)&gq,   g_q);
    cudaGetSymbolAddress((void**)&gk,   g_k);
    cudaGetSymbolAddress((void**)&gv,   g_v);
    cudaGetSymbolAddress((void**)&gQp,  g_Qp);
    cudaGetSymbolAddress((void**)&gKp,  g_Kp);
    cudaGetSymbolAddress((void**)&gVp,  g_Vp);
    cudaGetSymbolAddress((void**)&gVal, g_Val);
    cudaGetSymbolAddress((void**)&gS,   g_S);
    cudaGetSymbolAddress((void**)&gPart,g_part);
    cudaGetSymbolAddress((void**)&gAtt, g_att);
    cudaGetSymbolAddress((void**)&gXs1, g_xs1);
    cudaGetSymbolAddress((void**)&gFf,  g_ff);

    dim3 blk(256);
    dim3 cgrid(NIMG * 32, 2);

    // QKV projections (bias fused)
    mma_conv_kernel<<<cgrid, blk>>>(xs, Wq, bq, xs, gq, 1, 1, 0, 0);
    mma_conv_kernel<<<cgrid, blk>>>(xs, Wk, bk, xs, gk, 1, 1, 0, 0);
    mma_conv_kernel<<<cgrid, blk>>>(xs, Wv, bv, xs, gv, 1, 1, 0, 0);

    // --- scales P=32,16,8: SIMT path ---
    const int PS[3]     = {32, 16, 8};
    const int SPLITK[3] = {64, 16, 2};
    for (int s = 0; s < 3; s++) {
        const int P = PS[s], o = 64 / P, n = 8 * o * o, d = 64 * P * P, c0 = s * 64;
        const int splitk = SPLITK[s];
        const int total = 2 * n * d;
        patchify_kernel<<<total / 256, blk>>>(gq, gQp, P, c0);
        patchify_kernel<<<total / 256, blk>>>(gk, gKp, P, c0);
        patchify_kernel<<<total / 256, blk>>>(gv, gVp, P, c0);

        float* Cdst = (splitk > 1) ? gPart : gS;
        dim3 gsc((n + 63) / 64, (n + 63) / 64, 2 * splitk);
        gemm_nt_kernel<<<gsc, blk>>>(gQp, gKp, Cdst, n, n, d, splitk);
        if (splitk > 1)
            reduce_splitk_kernel<<<(2 * n * n) / 256, blk>>>(gPart, gS, n * n, splitk);

        softmax_kernel<<<2 * n, blk>>>(gS, n, 1.0f / sqrtf((float)d));

        dim3 gav((d + 63) / 64, (n + 63) / 64, 2);
        gemm_nn_kernel<<<gav, blk>>>(gS, gVp, gVal, n, d, n, n, d, d,
                                     (long)n * n, (long)n * d, (long)n * d);
        unpatchify_kernel<<<total / 256, blk>>>(gVal, gAtt, P, c0);
    }

    // --- scale P=4: tensor-core path (n=2048, d=1024) ---
    {
        const int P = 4, n = 2048, d = 1024, c0 = 192;
        const int total = 2 * n * d;
        patchify_kernel<<<total / 256, blk>>>(gq, gQp, P, c0);
        patchify_kernel<<<total / 256, blk>>>(gk, gKp, P, c0);
        patchify_kernel<<<total / 256, blk>>>(gv, gVp, P, c0);

        mma_nt_kernel<<<dim3(n / 128, n / 128, 2), blk>>>(
            gQp, gKp, gS, n, d, (long)n * d, (long)n * d, (long)n * n);
        softmax_kernel<<<2 * n, blk>>>(gS, n, 1.0f / sqrtf((float)d));
        mma_nn_kernel<<<dim3(d / 128, n / 128, 2), blk>>>(
            gS, gVp, gVal, d, n, (long)n * n, (long)n * d, (long)n * d);
        unpatchify_kernel<<<total / 256, blk>>>(gVal, gAtt, P, c0);
    }

    // convs (bias + leaky + residual fused)
    mma_conv_kernel<<<cgrid, blk>>>(gAtt, Wl, bl, xs,   gXs1, 3, 1, 1, 1);
    mma_conv_kernel<<<cgrid, blk>>>(gXs1, Wf1, bf1, xs, gFf,  3, 1, 1, 0);
    mma_conv_kernel<<<cgrid, blk>>>(gFf,  Wf2, bf2, gXs1, out, 3, 2, 1, 1);
}

// round 4
// speedup vs baseline: 5.3399x; 1.3926x over previous
#include <cuda_runtime.h>
#include <cuda_fp16.h>
#include <math.h>
#include <stdint.h>

#define NIMG 16
#define CCH 256
#define NPIX 4096            // 64*64

// ---- scratch (static device globals; no allocation) ----
// patchified Q/K/V: 4 scale regions of 4194304 floats each = [b][token][d]
__device__ float g_Qp[16777216];
__device__ float g_Kp[16777216];
__device__ float g_Vp[16777216];
__device__ float g_S[2*2048*2048];
__device__ float g_part[1048576];
__device__ float g_att[NIMG*CCH*NPIX];
__device__ float g_xs1[NIMG*CCH*NPIX];
__device__ float g_ff[NIMG*CCH*NPIX];

// ============================================================================
// mma helpers
// ============================================================================
__device__ __forceinline__ uint32_t f2tf(float x) {
    uint32_t u;
    asm("cvt.rna.tf32.f32 %0, %1;" : "=r"(u) : "f"(x));
    return u;
}

__device__ __forceinline__ void mma8(float* d, const uint32_t* a, const uint32_t* b) {
    asm volatile(
        "mma.sync.aligned.m16n8k8.row.col.f32.tf32.tf32.f32 "
        "{%0,%1,%2,%3}, {%4,%5,%6,%7}, {%8,%9}, {%0,%1,%2,%3};"
        : "+f"(d[0]), "+f"(d[1]), "+f"(d[2]), "+f"(d[3])
        : "r"(a[0]), "r"(a[1]), "r"(a[2]), "r"(a[3]), "r"(b[0]), "r"(b[1]));
}

__device__ __forceinline__ void mma16(float* d, const uint32_t* a, const uint32_t* b) {
    asm volatile(
        "mma.sync.aligned.m16n8k16.row.col.f32.f16.f16.f32 "
        "{%0,%1,%2,%3}, {%4,%5,%6,%7}, {%8,%9}, {%0,%1,%2,%3};"
        : "+f"(d[0]), "+f"(d[1]), "+f"(d[2]), "+f"(d[3])
        : "r"(a[0]), "r"(a[1]), "r"(a[2]), "r"(a[3]), "r"(b[0]), "r"(b[1]));
}

__device__ __forceinline__ void ldsm4(uint32_t* r, const void* p) {
    uint32_t addr = (uint32_t)__cvta_generic_to_shared(p);
    asm volatile("ldmatrix.sync.aligned.m8n8.x4.shared.b16 {%0,%1,%2,%3}, [%4];"
        : "=r"(r[0]), "=r"(r[1]), "=r"(r[2]), "=r"(r[3]) : "r"(addr));
}

__device__ __forceinline__ uint32_t pack_h2(float a, float b) {
    __half2 h = __floats2half2_rn(a, b);
    return *(uint32_t*)&h;
}

// scatter index into patchified buffer: scale = oc>>6
__device__ __forceinline__ long pat_index(int img, int oc, int pix) {
    int s  = oc >> 6, cc = oc & 63;
    int lp = 5 - s;                 // log2 P: 5,4,3,2
    int lo = 1 + s;                 // log2 o
    int Pm = (1 << lp) - 1;
    int y = pix >> 6, x = pix & 63;
    int ohi = y >> lp, pi = y & Pm, owi = x >> lp, pj = x & Pm;
    int t = img & 7, b = img >> 3;
    int nn = (t << (2*lo)) + (ohi << lo) + owi;
    int dd = (cc << (2*lp)) + (pi << lp) + pj;
    return (long)s * 4194304 + (long)b * 2097152 + (long)nn * (64 << (2*lp)) + dd;
}

// ============================================================================
// fp16 mma conv / projection (implicit im2col), K-chunk 32, m16n8k16 + ldmatrix
//   patout=1: scatter-write patchified (QKV; bias only)
//   patout=0: image layout with bias + leaky + optional residual
// ============================================================================
__global__ void __launch_bounds__(256) hconv_kernel(
    const float* __restrict__ in, const float* __restrict__ Wt,
    const float* __restrict__ bias, const float* __restrict__ res,
    float* __restrict__ out, int ks, int dil, int do_leaky, int addres, int patout)
{
    __shared__ __half As[128 * 40];
    __shared__ __half Bs[128 * 40];
    const int tid = threadIdx.x;
    const int lane = tid & 31, wid = tid >> 5;
    const int wm = wid & 1, wn = wid >> 1;
    const int K = CCH * ks * ks;
    const int img = blockIdx.x >> 5;
    const int p0 = (blockIdx.x & 31) * 128;
    const int m0 = blockIdx.y * 128;
    const float* inimg = in + (long)img * CCH * NPIX;

    const int wr  = tid >> 1;          // tile row 0..127
    const int wkh = (tid & 1) * 16;    // k half
    const int py = (p0 + wr) >> 6, px = (p0 + wr) & 63;

    float acc[4][4][4] = {};

    for (int k0 = 0; k0 < K; k0 += 32) {
        __syncthreads();
        // A: weights [m][k] -> half
        {
            const float* src = Wt + (long)(m0 + wr) * K + k0 + wkh;
            uint32_t* ad = (uint32_t*)(As + wr * 40 + wkh);
#pragma unroll
            for (int i4 = 0; i4 < 4; i4++) {
                float4 v = *(const float4*)(src + i4 * 4);
                ad[i4*2 + 0] = pack_h2(v.x, v.y);
                ad[i4*2 + 1] = pack_h2(v.z, v.w);
            }
        }
        // B: implicit im2col [n][k] -> half
        {
            uint32_t* bd = (uint32_t*)(Bs + wr * 40 + wkh);
            if (ks == 1) {
#pragma unroll
                for (int i2 = 0; i2 < 8; i2++) {
                    float v0 = inimg[(k0 + wkh + 2*i2    ) * NPIX + p0 + wr];
                    float v1 = inimg[(k0 + wkh + 2*i2 + 1) * NPIX + p0 + wr];
                    bd[i2] = pack_h2(v0, v1);
                }
            } else {
                float vv[16];
#pragma unroll
                for (int i = 0; i < 16; i++) {
                    int k = k0 + wkh + i;
                    int c = k / 9;
                    int tap = k - c * 9;
                    int ky = tap / 3, kx = tap - ky * 3;
                    int sy = py + (ky - 1) * dil;
                    int sx = px + (kx - 1) * dil;
                    float v = 0.f;
                    if ((unsigned)sy < 64u && (unsigned)sx < 64u)
                        v = inimg[(c << 12) + (sy << 6) + sx];
                    vv[i] = v;
                }
#pragma unroll
                for (int i2 = 0; i2 < 8; i2++)
                    bd[i2] = pack_h2(vv[2*i2], vv[2*i2 + 1]);
            }
        }
        __syncthreads();

#pragma unroll
        for (int kstep = 0; kstep < 2; kstep++) {
            uint32_t a[4][4], b[4][2];
            // A fragments: 4 m-tiles of 16 rows
            {
                const int arow = wm * 64 + ((lane >> 3) & 1) * 8 + (lane & 7);
                const int akc  = kstep * 16 + (lane >> 4) * 8;
#pragma unroll
                for (int mi = 0; mi < 4; mi++)
                    ldsm4(a[mi], As + (arow + mi * 16) * 40 + akc);
            }
            // B fragments: 2 ldmatrix.x4 cover 4 n8 tiles
            {
                const int bkc = kstep * 16 + ((lane >> 3) & 1) * 8;
#pragma unroll
                for (int ni2 = 0; ni2 < 2; ni2++) {
                    const int brow = wn * 32 + ni2 * 16 + ((lane >> 4) & 1) * 8 + (lane & 7);
                    uint32_t r[4];
                    ldsm4(r, Bs + brow * 40 + bkc);
                    b[2*ni2    ][0] = r[0]; b[2*ni2    ][1] = r[1];
                    b[2*ni2 + 1][0] = r[2]; b[2*ni2 + 1][1] = r[3];
                }
            }
#pragma unroll
            for (int mi = 0; mi < 4; mi++)
#pragma unroll
                for (int ni = 0; ni < 4; ni++)
                    mma16(acc[mi][ni], a[mi], b[ni]);
        }
    }

    const int orow = m0 + wm * 64 + (lane >> 2);
    const int ocol = p0 + wn * 32 + (lane & 3) * 2;

    if (patout) {
        // scatter into patchified layout; n even -> pj even -> idx+1 same patch row
#pragma unroll
        for (int mi = 0; mi < 4; mi++) {
            const int oca = orow + mi * 16, ocb = oca + 8;
            const float ba = bias[oca], bb = bias[ocb];
#pragma unroll
            for (int ni = 0; ni < 4; ni++) {
                const int n = ocol + ni * 8;
                long ia = pat_index(img, oca, n);
                long ib = pat_index(img, ocb, n);
                out[ia]     = acc[mi][ni][0] + ba;
                out[ia + 1] = acc[mi][ni][1] + ba;
                out[ib]     = acc[mi][ni][2] + bb;
                out[ib + 1] = acc[mi][ni][3] + bb;
            }
        }
    } else {
#pragma unroll
        for (int mi = 0; mi < 4; mi++) {
            const int oca = orow + mi * 16;
            const int ocb = oca + 8;
            const float ba = bias[oca], bb = bias[ocb];
#pragma unroll
            for (int ni = 0; ni < 4; ni++) {
                const int n = ocol + ni * 8;
                long ia = ((long)img * 256 + oca) * NPIX + n;
                long ib = ((long)img * 256 + ocb) * NPIX + n;
                float v0 = acc[mi][ni][0] + ba, v1 = acc[mi][ni][1] + ba;
                float v2 = acc[mi][ni][2] + bb, v3 = acc[mi][ni][3] + bb;
                if (do_leaky) {
                    v0 = (v0 > 0.f) ? v0 : 0.2f * v0;
                    v1 = (v1 > 0.f) ? v1 : 0.2f * v1;
                    v2 = (v2 > 0.f) ? v2 : 0.2f * v2;
                    v3 = (v3 > 0.f) ? v3 : 0.2f * v3;
                }
                if (addres) {
                    v0 += res[ia]; v1 += res[ia + 1];
                    v2 += res[ib]; v3 += res[ib + 1];
                }
                out[ia] = v0; out[ia + 1] = v1;
                out[ib] = v2; out[ib + 1] = v3;
            }
        }
    }
}

// ============================================================================
// mma NT GEMM (tf32): C[z][m][n] = sum_k A[z][m*K+k] * B[z][n*K+k]
// ============================================================================
__global__ void __launch_bounds__(256) mma_nt_kernel(
    const float* __restrict__ A, const float* __restrict__ B, float* __restrict__ C,
    int N, int K, long sA, long sB, long sC)
{
    __shared__ uint32_t As[128][36];
    __shared__ uint32_t Bs[128][36];
    const int tid = threadIdx.x;
    const int lane = tid & 31, wid = tid >> 5;
    const int wm = wid & 1, wn = wid >> 1;
    const int n0 = blockIdx.x * 128, m0 = blockIdx.y * 128;
    A += (long)blockIdx.z * sA;
    B += (long)blockIdx.z * sB;
    C += (long)blockIdx.z * sC;

    const int wr = tid >> 1;
    const int wkh = (tid & 1) * 16;

    float acc[4][4][4] = {};
    for (int k0 = 0; k0 < K; k0 += 32) {
        __syncthreads();
        {
            const float* sa = A + (long)(m0 + wr) * K + k0 + wkh;
            const float* sb = B + (long)(n0 + wr) * K + k0 + wkh;
#pragma unroll
            for (int i = 0; i < 4; i++) {
                float4 va = *(const float4*)(sa + i * 4);
                float4 vb = *(const float4*)(sb + i * 4);
                As[wr][wkh + i*4 + 0] = f2tf(va.x);
                As[wr][wkh + i*4 + 1] = f2tf(va.y);
                As[wr][wkh + i*4 + 2] = f2tf(va.z);
                As[wr][wkh + i*4 + 3] = f2tf(va.w);
                Bs[wr][wkh + i*4 + 0] = f2tf(vb.x);
                Bs[wr][wkh + i*4 + 1] = f2tf(vb.y);
                Bs[wr][wkh + i*4 + 2] = f2tf(vb.z);
                Bs[wr][wkh + i*4 + 3] = f2tf(vb.w);
            }
        }
        __syncthreads();
#pragma unroll
        for (int s8 = 0; s8 < 4; s8++) {
            const int ac = s8 * 8 + (lane & 3);
            const int ar = wm * 64 + (lane >> 2);
            const int bn = wn * 32 + (lane >> 2);
            uint32_t a[4][4], b[4][2];
#pragma unroll
            for (int mi = 0; mi < 4; mi++) {
                a[mi][0] = As[ar + mi*16    ][ac];
                a[mi][1] = As[ar + mi*16 + 8][ac];
                a[mi][2] = As[ar + mi*16    ][ac + 4];
                a[mi][3] = As[ar + mi*16 + 8][ac + 4];
            }
#pragma unroll
            for (int ni = 0; ni < 4; ni++) {
                b[ni][0] = Bs[bn + ni*8][ac];
                b[ni][1] = Bs[bn + ni*8][ac + 4];
            }
#pragma unroll
            for (int mi = 0; mi < 4; mi++)
#pragma unroll
                for (int ni = 0; ni < 4; ni++)
                    mma8(acc[mi][ni], a[mi], b[ni]);
        }
    }
    const int orow = m0 + wm * 64 + (lane >> 2);
    const int ocol = n0 + wn * 32 + (lane & 3) * 2;
#pragma unroll
    for (int mi = 0; mi < 4; mi++) {
        long ra = (long)(orow + mi * 16) * N;
        long rb = (long)(orow + mi * 16 + 8) * N;
#pragma unroll
        for (int ni = 0; ni < 4; ni++) {
            int n = ocol + ni * 8;
            C[ra + n] = acc[mi][ni][0]; C[ra + n + 1] = acc[mi][ni][1];
            C[rb + n] = acc[mi][ni][2]; C[rb + n + 1] = acc[mi][ni][3];
        }
    }
}

// ============================================================================
// mma NN GEMM (tf32), P=4 AV, scatter epilogue to image layout (c0=192)
//   A[z] = S (2048x2048), B[z] = Vp (2048x1024), out = att image
// ============================================================================
__global__ void __launch_bounds__(256) mma_av4_kernel(
    const float* __restrict__ A, const float* __restrict__ B, float* __restrict__ out,
    int N, int K, long sA, long sB)
{
    __shared__ uint32_t As[128][36];
    __shared__ uint32_t Bs[32][132];
    const int tid = threadIdx.x;
    const int lane = tid & 31, wid = tid >> 5;
    const int wm = wid & 1, wn = wid >> 1;
    const int n0 = blockIdx.x * 128, m0 = blockIdx.y * 128;
    const int z = blockIdx.z;
    A += (long)z * sA;
    B += (long)z * sB;

    const int wr = tid >> 1;
    const int wkh = (tid & 1) * 16;
    const int bk = tid >> 3;
    const int bn = (tid & 7) * 16;

    float acc[4][4][4] = {};
    for (int k0 = 0; k0 < K; k0 += 32) {
        __syncthreads();
        {
            const float* sa = A + (long)(m0 + wr) * K + k0 + wkh;
#pragma unroll
            for (int i = 0; i < 4; i++) {
                float4 va = *(const float4*)(sa + i * 4);
                As[wr][wkh + i*4 + 0] = f2tf(va.x);
                As[wr][wkh + i*4 + 1] = f2tf(va.y);
                As[wr][wkh + i*4 + 2] = f2tf(va.z);
                As[wr][wkh + i*4 + 3] = f2tf(va.w);
            }
            const float* sb = B + (long)(k0 + bk) * N + n0 + bn;
#pragma unroll
            for (int i = 0; i < 4; i++) {
                float4 vb = *(const float4*)(sb + i * 4);
                Bs[bk][bn + i*4 + 0] = f2tf(vb.x);
                Bs[bk][bn + i*4 + 1] = f2tf(vb.y);
                Bs[bk][bn + i*4 + 2] = f2tf(vb.z);
                Bs[bk][bn + i*4 + 3] = f2tf(vb.w);
            }
        }
        __syncthreads();
#pragma unroll
        for (int s8 = 0; s8 < 4; s8++) {
            const int ac = s8 * 8 + (lane & 3);
            const int ar = wm * 64 + (lane >> 2);
            const int bc = wn * 32 + (lane >> 2);
            uint32_t a[4][4], b[4][2];
#pragma unroll
            for (int mi = 0; mi < 4; mi++) {
                a[mi][0] = As[ar + mi*16    ][ac];
                a[mi][1] = As[ar + mi*16 + 8][ac];
                a[mi][2] = As[ar + mi*16    ][ac + 4];
                a[mi][3] = As[ar + mi*16 + 8][ac + 4];
            }
#pragma unroll
            for (int ni = 0; ni < 4; ni++) {
                b[ni][0] = Bs[ac    ][bc + ni*8];
                b[ni][1] = Bs[ac + 4][bc + ni*8];
            }
#pragma unroll
            for (int mi = 0; mi < 4; mi++)
#pragma unroll
                for (int ni = 0; ni < 4; ni++)
                    mma8(acc[mi][ni], a[mi], b[ni]);
        }
    }
    // scatter: m = token, col = dd  (P=4, c0=192)
    const int orow = m0 + wm * 64 + (lane >> 2);
    const int ocol = n0 + wn * 32 + (lane & 3) * 2;
#pragma unroll
    for (int mi = 0; mi < 4; mi++) {
#pragma unroll
        for (int half = 0; half < 2; half++) {
            const int m = orow + mi * 16 + half * 8;
            const int t = m >> 8, r = m & 255, ohi = r >> 4, owi = r & 15;
#pragma unroll
            for (int ni = 0; ni < 4; ni++) {
                const int col = ocol + ni * 8;
                const int cc = col >> 4, rr = col & 15, pi = rr >> 2, pj = rr & 3;
                long dst = ((long)((z * 8 + t) * 256 + 192 + cc) << 12)
                         + (((ohi << 2) + pi) << 6) + (owi << 2) + pj;
                out[dst]     = acc[mi][ni][half * 2];
                out[dst + 1] = acc[mi][ni][half * 2 + 1];
            }
        }
    }
}

// ===================== SIMT SGEMM (NT), deterministic split-K =====================
__global__ void __launch_bounds__(256) gemm_nt_kernel(
    const float* __restrict__ A, const float* __restrict__ B, float* __restrict__ Cm,
    int M, int N, int K, int splitk)
{
    const int z = blockIdx.z;
    const int batch = z / splitk, ks = z - batch * splitk;
    A  += (long)batch * M * K;
    B  += (long)batch * N * K;
    Cm += (long)z * M * N;
    const int kchunk = K / splitk;
    const int kbeg = ks * kchunk;
    const int m0 = blockIdx.y * 64, n0 = blockIdx.x * 64;
    __shared__ __align__(16) float As[16][68];
    __shared__ __align__(16) float Bs[16][68];
    const int tid = threadIdx.x;
    const int tx = tid & 15, ty = tid >> 4;
    float acc[4][4] = {};
    for (int k0 = kbeg; k0 < kbeg + kchunk; k0 += 16) {
#pragma unroll
        for (int it = 0; it < 4; it++) {
            int id = tid + it * 256;
            int m = id >> 4, kk = id & 15;
            As[kk][m] = (m0 + m < M) ? A[(long)(m0 + m) * K + k0 + kk] : 0.f;
        }
#pragma unroll
        for (int it = 0; it < 4; it++) {
            int id = tid + it * 256;
            int nn = id >> 4, kk = id & 15;
            Bs[kk][nn] = (n0 + nn < N) ? B[(long)(n0 + nn) * K + k0 + kk] : 0.f;
        }
        __syncthreads();
#pragma unroll
        for (int kk = 0; kk < 16; kk++) {
            float4 a4 = *(const float4*)&As[kk][ty * 4];
            float4 b4 = *(const float4*)&Bs[kk][tx * 4];
            float ar[4] = {a4.x, a4.y, a4.z, a4.w};
            float br[4] = {b4.x, b4.y, b4.z, b4.w};
#pragma unroll
            for (int i = 0; i < 4; i++)
#pragma unroll
                for (int j = 0; j < 4; j++)
                    acc[i][j] += ar[i] * br[j];
        }
        __syncthreads();
    }
#pragma unroll
    for (int i = 0; i < 4; i++) {
        int m = m0 + ty * 4 + i;
        if (m >= M) continue;
#pragma unroll
        for (int j = 0; j < 4; j++) {
            int nn = n0 + tx * 4 + j;
            if (nn < N) Cm[(long)m * N + nn] = acc[i][j];
        }
    }
}

__global__ void reduce_splitk_kernel(const float* __restrict__ part, float* __restrict__ S,
                                     int per, int splitk)
{
    long idx = (long)blockIdx.x * 256 + threadIdx.x;
    int b = (int)(idx / per);
    int r = (int)(idx - (long)b * per);
    float s = 0.f;
    for (int ks = 0; ks < splitk; ks++)
        s += part[(long)(b * splitk + ks) * per + r];
    S[idx] = s;
}

// ===================== SIMT AV GEMM with scatter epilogue =========================
// out_img[(z*8+t)*256 + c0+cc][y][x] = sum_k S[z][m][k] * Vp[z][k][dd]
__global__ void __launch_bounds__(256) gemm_av_kernel(
    const float* __restrict__ A, const float* __restrict__ B, float* __restrict__ out,
    int n, int d, int lp, int c0)
{
    const int z = blockIdx.z;
    A += (long)z * n * n;
    B += (long)z * n * d;
    const int m0 = blockIdx.y * 64, n0 = blockIdx.x * 64;
    __shared__ __align__(16) float As[16][68];
    __shared__ __align__(16) float Bs[16][64];
    const int tid = threadIdx.x;
    const int tx = tid & 15, ty = tid >> 4;
    float acc[4][4] = {};
    for (int k0 = 0; k0 < n; k0 += 16) {
#pragma unroll
        for (int it = 0; it < 4; it++) {
            int id = tid + it * 256;
            int m = id >> 4, kk = id & 15;
            As[kk][m] = (m0 + m < n) ? A[(long)(m0 + m) * n + k0 + kk] : 0.f;
        }
#pragma unroll
        for (int it = 0; it < 4; it++) {
            int id = tid + it * 256;
            int kk = id >> 6, nn = id & 63;
            Bs[kk][nn] = (k0 + kk < n) ? B[(long)(k0 + kk) * d + n0 + nn] : 0.f;
        }
        __syncthreads();
#pragma unroll
        for (int kk = 0; kk < 16; kk++) {
            float4 a4 = *(const float4*)&As[kk][ty * 4];
            float4 b4 = *(const float4*)&Bs[kk][tx * 4];
            float ar[4] = {a4.x, a4.y, a4.z, a4.w};
            float br[4] = {b4.x, b4.y, b4.z, b4.w};
#pragma unroll
            for (int i = 0; i < 4; i++)
#pragma unroll
                for (int j = 0; j < 4; j++)
                    acc[i][j] += ar[i] * br[j];
        }
        __syncthreads();
    }
    const int lo = 6 - lp, o = 1 << lo, P = 1 << lp;
#pragma unroll
    for (int i = 0; i < 4; i++) {
        int m = m0 + ty * 4 + i;
        if (m >= n) continue;
        int t = m >> (2 * lo);
        int r = m & ((1 << (2 * lo)) - 1);
        int ohi = r >> lo, owi = r & (o - 1);
        // base column: 4 consecutive dd stay within one patch row (P>=8, col%4==0)
        int col = n0 + tx * 4;
        int cc = col >> (2 * lp);
        int rr = col & (P * P - 1);
        int pi = rr >> lp, pj = rr & (P - 1);
        long dst = ((long)((z * 8 + t) * 256 + c0 + cc) << 12)
                 + (((ohi << lp) + pi) << 6) + (owi << lp) + pj;
#pragma unroll
        for (int j = 0; j < 4; j++)
            out[dst + j] = acc[i][j];
    }
}

// ===================== softmax (row-wise, scale folded in) ========================
__global__ void softmax_kernel(float* __restrict__ S, int n, float scale)
{
    __shared__ float buf[2048];
    __shared__ float red[256];
    const long row = blockIdx.x;
    float* p = S + row * (long)n;
    const int tid = threadIdx.x;
    float m = -1e30f;
    for (int i = tid; i < n; i += 256) { float v = p[i] * scale; buf[i] = v; m = fmaxf(m, v); }
    red[tid] = m; __syncthreads();
    for (int s = 128; s > 0; s >>= 1) { if (tid < s) red[tid] = fmaxf(red[tid], red[tid + s]); __syncthreads(); }
    m = red[0]; __syncthreads();
    float sum = 0.f;
    for (int i = tid; i < n; i += 256) { float e = expf(buf[i] - m); buf[i] = e; sum += e; }
    red[tid] = sum; __syncthreads();
    for (int s = 128; s > 0; s >>= 1) { if (tid < s) red[tid] += red[tid + s]; __syncthreads(); }
    float inv = 1.f / red[0];
    for (int i = tid; i < n; i += 256) p[i] = buf[i] * inv;
}

// ===================== launcher ===================================================
extern "C" void kernel_launch(void* const* d_in, const int* in_sizes, int n_in,
                              void* d_out, int out_size)
{
    const float* xs  = (const float*)d_in[0];
    const float* Wq  = (const float*)d_in[2];
    const float* bq  = (const float*)d_in[3];
    const float* Wk  = (const float*)d_in[4];
    const float* bk  = (const float*)d_in[5];
    const float* Wv  = (const float*)d_in[6];
    const float* bv  = (const float*)d_in[7];
    const float* Wl  = (const float*)d_in[8];
    const float* bl  = (const float*)d_in[9];
    const float* Wf1 = (const float*)d_in[10];
    const float* bf1 = (const float*)d_in[11];
    const float* Wf2 = (const float*)d_in[12];
    const float* bf2 = (const float*)d_in[13];
    float* out = (float*)d_out;

    float *gQp, *gKp, *gVp, *gS, *gPart, *gAtt, *gXs1, *gFf;
    cudaGetSymbolAddress((void**)&gQp,  g_Qp);
    cudaGetSymbolAddress((void**)&gKp,  g_Kp);
    cudaGetSymbolAddress((void**)&gVp,  g_Vp);
    cudaGetSymbolAddress((void**)&gS,   g_S);
    cudaGetSymbolAddress((void**)&gPart,g_part);
    cudaGetSymbolAddress((void**)&gAtt, g_att);
    cudaGetSymbolAddress((void**)&gXs1, g_xs1);
    cudaGetSymbolAddress((void**)&gFf,  g_ff);

    dim3 blk(256);
    dim3 cgrid(NIMG * 32, 2);

    // QKV projections -> patchified layout directly (bias fused)
    hconv_kernel<<<cgrid, blk>>>(xs, Wq, bq, nullptr, gQp, 1, 1, 0, 0, 1);
    hconv_kernel<<<cgrid, blk>>>(xs, Wk, bk, nullptr, gKp, 1, 1, 0, 0, 1);
    hconv_kernel<<<cgrid, blk>>>(xs, Wv, bv, nullptr, gVp, 1, 1, 0, 0, 1);

    // --- scales P=32,16,8: SIMT path (AV scatter-writes image layout) ---
    const int LP[3]     = {5, 4, 3};
    const int SPLITK[3] = {64, 16, 2};
    for (int s = 0; s < 3; s++) {
        const int lp = LP[s], P = 1 << lp, o = 64 / P;
        const int n = 8 * o * o, d = 64 * P * P, c0 = s * 64;
        const long soff = (long)s * 4194304;
        const int splitk = SPLITK[s];

        float* Cdst = (splitk > 1) ? gPart : gS;
        dim3 gsc((n + 63) / 64, (n + 63) / 64, 2 * splitk);
        gemm_nt_kernel<<<gsc, blk>>>(gQp + soff, gKp + soff, Cdst, n, n, d, splitk);
        if (splitk > 1)
            reduce_splitk_kernel<<<(2 * n * n) / 256, blk>>>(gPart, gS, n * n, splitk);

        softmax_kernel<<<2 * n, blk>>>(gS, n, 1.0f / sqrtf((float)d));

        dim3 gav((d + 63) / 64, (n + 63) / 64, 2);
        gemm_av_kernel<<<gav, blk>>>(gS, gVp + soff, gAtt, n, d, lp, c0);
    }

    // --- scale P=4: tensor-core path (n=2048, d=1024), AV scatter ---
    {
        const int n = 2048, d = 1024;
        const long soff = 3L * 4194304;
        mma_nt_kernel<<<dim3(n / 128, n / 128, 2), blk>>>(
            gQp + soff, gKp + soff, gS, n, d, (long)n * d, (long)n * d, (long)n * n);
        softmax_kernel<<<2 * n, blk>>>(gS, n, 1.0f / sqrtf((float)d));
        mma_av4_kernel<<<dim3(d / 128, n / 128, 2), blk>>>(
            gS, gVp + soff, gAtt, d, n, (long)n * n, (long)n * d);
    }

    // convs (bias + leaky + residual fused)
    hconv_kernel<<<cgrid, blk>>>(gAtt, Wl, bl, xs,   gXs1, 3, 1, 1, 1, 0);
    hconv_kernel<<<cgrid, blk>>>(gXs1, Wf1, bf1, xs, gFf,  3, 1, 1, 0, 0);
    hconv_kernel<<<cgrid, blk>>>(gFf,  Wf2, bf2, gXs1, out, 3, 2, 1, 1, 0);
}

// round 5
// speedup vs baseline: 5.7339x; 1.0738x over previous
#include <cuda_runtime.h>
#include <cuda_fp16.h>
#include <math.h>
#include <stdint.h>

#define NIMG 16
#define CCH 256
#define NPIX 4096            // 64*64

// ---- scratch (static device globals; no allocation) ----
// patchified Q/K/V (half): 4 scale regions of 4194304 elems = [b][token][d]
__device__ __half g_Qp[16777216];
__device__ __half g_Kp[16777216];
__device__ __half g_Vp[16777216];
__device__ float g_S[2*2048*2048];
__device__ float g_part[8388608];
__device__ float g_att[NIMG*CCH*NPIX];
__device__ float g_xs1[NIMG*CCH*NPIX];
__device__ float g_ff[NIMG*CCH*NPIX];

// ============================================================================
// mma helpers (fp16 m16n8k16, f32 accum; arch-neutral PTX)
// ============================================================================
__device__ __forceinline__ void mma16(float* d, const uint32_t* a, const uint32_t* b) {
    asm volatile(
        "mma.sync.aligned.m16n8k16.row.col.f32.f16.f16.f32 "
        "{%0,%1,%2,%3}, {%4,%5,%6,%7}, {%8,%9}, {%0,%1,%2,%3};"
        : "+f"(d[0]), "+f"(d[1]), "+f"(d[2]), "+f"(d[3])
        : "r"(a[0]), "r"(a[1]), "r"(a[2]), "r"(a[3]), "r"(b[0]), "r"(b[1]));
}

__device__ __forceinline__ void ldsm4(uint32_t* r, const void* p) {
    uint32_t addr = (uint32_t)__cvta_generic_to_shared(p);
    asm volatile("ldmatrix.sync.aligned.m8n8.x4.shared.b16 {%0,%1,%2,%3}, [%4];"
        : "=r"(r[0]), "=r"(r[1]), "=r"(r[2]), "=r"(r[3]) : "r"(addr));
}

__device__ __forceinline__ void ldsm4t(uint32_t* r, const void* p) {
    uint32_t addr = (uint32_t)__cvta_generic_to_shared(p);
    asm volatile("ldmatrix.sync.aligned.m8n8.x4.trans.shared.b16 {%0,%1,%2,%3}, [%4];"
        : "=r"(r[0]), "=r"(r[1]), "=r"(r[2]), "=r"(r[3]) : "r"(addr));
}

__device__ __forceinline__ uint32_t pack_h2(float a, float b) {
    __half2 h = __floats2half2_rn(a, b);
    return *(uint32_t*)&h;
}

// scatter index into patchified buffer: scale = oc>>6
__device__ __forceinline__ long pat_index(int img, int oc, int pix) {
    int s  = oc >> 6, cc = oc & 63;
    int lp = 5 - s;                 // log2 P: 5,4,3,2
    int lo = 1 + s;                 // log2 o
    int Pm = (1 << lp) - 1;
    int y = pix >> 6, x = pix & 63;
    int ohi = y >> lp, pi = y & Pm, owi = x >> lp, pj = x & Pm;
    int t = img & 7, b = img >> 3;
    int nn = (t << (2*lo)) + (ohi << lo) + owi;
    int dd = (cc << (2*lp)) + (pi << lp) + pj;
    return (long)s * 4194304 + (long)b * 2097152 + (long)nn * (64 << (2*lp)) + dd;
}

// ============================================================================
// fp16 mma conv / projection (implicit im2col), K-chunk 32, m16n8k16 + ldmatrix
//   patout=1: scatter-write patchified half buffer (QKV; bias only)
//   patout=0: f32 image layout with bias + leaky + optional residual
// ============================================================================
__global__ void __launch_bounds__(256) hconv_kernel(
    const float* __restrict__ in, const float* __restrict__ Wt,
    const float* __restrict__ bias, const float* __restrict__ res,
    float* __restrict__ out, __half* __restrict__ outh,
    int ks, int dil, int do_leaky, int addres, int patout)
{
    __shared__ __half As[128 * 40];
    __shared__ __half Bs[128 * 40];
    const int tid = threadIdx.x;
    const int lane = tid & 31, wid = tid >> 5;
    const int wm = wid & 1, wn = wid >> 1;
    const int K = CCH * ks * ks;
    const int img = blockIdx.x >> 5;
    const int p0 = (blockIdx.x & 31) * 128;
    const int m0 = blockIdx.y * 128;
    const float* inimg = in + (long)img * CCH * NPIX;

    const int wr  = tid >> 1;
    const int wkh = (tid & 1) * 16;
    const int py = (p0 + wr) >> 6, px = (p0 + wr) & 63;

    float acc[4][4][4] = {};

    for (int k0 = 0; k0 < K; k0 += 32) {
        __syncthreads();
        {
            const float* src = Wt + (long)(m0 + wr) * K + k0 + wkh;
            uint32_t* ad = (uint32_t*)(As + wr * 40 + wkh);
#pragma unroll
            for (int i4 = 0; i4 < 4; i4++) {
                float4 v = *(const float4*)(src + i4 * 4);
                ad[i4*2 + 0] = pack_h2(v.x, v.y);
                ad[i4*2 + 1] = pack_h2(v.z, v.w);
            }
        }
        {
            uint32_t* bd = (uint32_t*)(Bs + wr * 40 + wkh);
            if (ks == 1) {
#pragma unroll
                for (int i2 = 0; i2 < 8; i2++) {
                    float v0 = inimg[(k0 + wkh + 2*i2    ) * NPIX + p0 + wr];
                    float v1 = inimg[(k0 + wkh + 2*i2 + 1) * NPIX + p0 + wr];
                    bd[i2] = pack_h2(v0, v1);
                }
            } else {
                float vv[16];
#pragma unroll
                for (int i = 0; i < 16; i++) {
                    int k = k0 + wkh + i;
                    int c = k / 9;
                    int tap = k - c * 9;
                    int ky = tap / 3, kx = tap - ky * 3;
                    int sy = py + (ky - 1) * dil;
                    int sx = px + (kx - 1) * dil;
                    float v = 0.f;
                    if ((unsigned)sy < 64u && (unsigned)sx < 64u)
                        v = inimg[(c << 12) + (sy << 6) + sx];
                    vv[i] = v;
                }
#pragma unroll
                for (int i2 = 0; i2 < 8; i2++)
                    bd[i2] = pack_h2(vv[2*i2], vv[2*i2 + 1]);
            }
        }
        __syncthreads();

#pragma unroll
        for (int kstep = 0; kstep < 2; kstep++) {
            uint32_t a[4][4], b[4][2];
            {
                const int arow = wm * 64 + ((lane >> 3) & 1) * 8 + (lane & 7);
                const int akc  = kstep * 16 + (lane >> 4) * 8;
#pragma unroll
                for (int mi = 0; mi < 4; mi++)
                    ldsm4(a[mi], As + (arow + mi * 16) * 40 + akc);
            }
            {
                const int bkc = kstep * 16 + ((lane >> 3) & 1) * 8;
#pragma unroll
                for (int ni2 = 0; ni2 < 2; ni2++) {
                    const int brow = wn * 32 + ni2 * 16 + ((lane >> 4) & 1) * 8 + (lane & 7);
                    uint32_t r[4];
                    ldsm4(r, Bs + brow * 40 + bkc);
                    b[2*ni2    ][0] = r[0]; b[2*ni2    ][1] = r[1];
                    b[2*ni2 + 1][0] = r[2]; b[2*ni2 + 1][1] = r[3];
                }
            }
#pragma unroll
            for (int mi = 0; mi < 4; mi++)
#pragma unroll
                for (int ni = 0; ni < 4; ni++)
                    mma16(acc[mi][ni], a[mi], b[ni]);
        }
    }

    const int orow = m0 + wm * 64 + (lane >> 2);
    const int ocol = p0 + wn * 32 + (lane & 3) * 2;

    if (patout) {
#pragma unroll
        for (int mi = 0; mi < 4; mi++) {
            const int oca = orow + mi * 16, ocb = oca + 8;
            const float ba = bias[oca], bb = bias[ocb];
#pragma unroll
            for (int ni = 0; ni < 4; ni++) {
                const int n = ocol + ni * 8;
                long ia = pat_index(img, oca, n);
                long ib = pat_index(img, ocb, n);
                *(__half2*)(outh + ia) = __floats2half2_rn(acc[mi][ni][0] + ba, acc[mi][ni][1] + ba);
                *(__half2*)(outh + ib) = __floats2half2_rn(acc[mi][ni][2] + bb, acc[mi][ni][3] + bb);
            }
        }
    } else {
#pragma unroll
        for (int mi = 0; mi < 4; mi++) {
            const int oca = orow + mi * 16;
            const int ocb = oca + 8;
            const float ba = bias[oca], bb = bias[ocb];
#pragma unroll
            for (int ni = 0; ni < 4; ni++) {
                const int n = ocol + ni * 8;
                long ia = ((long)img * 256 + oca) * NPIX + n;
                long ib = ((long)img * 256 + ocb) * NPIX + n;
                float v0 = acc[mi][ni][0] + ba, v1 = acc[mi][ni][1] + ba;
                float v2 = acc[mi][ni][2] + bb, v3 = acc[mi][ni][3] + bb;
                if (do_leaky) {
                    v0 = (v0 > 0.f) ? v0 : 0.2f * v0;
                    v1 = (v1 > 0.f) ? v1 : 0.2f * v1;
                    v2 = (v2 > 0.f) ? v2 : 0.2f * v2;
                    v3 = (v3 > 0.f) ? v3 : 0.2f * v3;
                }
                if (addres) {
                    v0 += res[ia]; v1 += res[ia + 1];
                    v2 += res[ib]; v3 += res[ib + 1];
                }
                out[ia] = v0; out[ia + 1] = v1;
                out[ib] = v2; out[ib + 1] = v3;
            }
        }
    }
}

// ============================================================================
// fp16 NT GEMM with deterministic split-K (scores):
//   C[z][m][n] = sum_k A[bat][m][k]*B[bat][n][k], z = bat*splitk + ks (f32 out)
// ============================================================================
__global__ void __launch_bounds__(256) hgemm_nt_kernel(
    const __half* __restrict__ A, const __half* __restrict__ B, float* __restrict__ C,
    int N, int K, int splitk, long sAB, long sC)
{
    __shared__ __half As[128 * 40];
    __shared__ __half Bs[128 * 40];
    const int tid = threadIdx.x;
    const int lane = tid & 31, wid = tid >> 5;
    const int wm = wid & 1, wn = wid >> 1;
    const int n0 = blockIdx.x * 128, m0 = blockIdx.y * 128;
    const int z = blockIdx.z, bat = z / splitk, ks = z - bat * splitk;
    A += (long)bat * sAB;
    B += (long)bat * sAB;
    C += (long)z * sC;
    const int kchunk = K / splitk, kbeg = ks * kchunk;
    const int wr = tid >> 1, wkh = (tid & 1) * 16;

    float acc[4][4][4] = {};
    for (int k0 = kbeg; k0 < kbeg + kchunk; k0 += 32) {
        __syncthreads();
        {
            const __half* sa = A + (long)(m0 + wr) * K + k0 + wkh;
            const __half* sb = B + (long)(n0 + wr) * K + k0 + wkh;
            *(uint4*)(As + wr * 40 + wkh)     = *(const uint4*)sa;
            *(uint4*)(As + wr * 40 + wkh + 8) = *(const uint4*)(sa + 8);
            *(uint4*)(Bs + wr * 40 + wkh)     = *(const uint4*)sb;
            *(uint4*)(Bs + wr * 40 + wkh + 8) = *(const uint4*)(sb + 8);
        }
        __syncthreads();
#pragma unroll
        for (int kstep = 0; kstep < 2; kstep++) {
            uint32_t a[4][4], b[4][2];
            {
                const int arow = wm * 64 + ((lane >> 3) & 1) * 8 + (lane & 7);
                const int akc  = kstep * 16 + (lane >> 4) * 8;
#pragma unroll
                for (int mi = 0; mi < 4; mi++)
                    ldsm4(a[mi], As + (arow + mi * 16) * 40 + akc);
            }
            {
                const int bkc = kstep * 16 + ((lane >> 3) & 1) * 8;
#pragma unroll
                for (int ni2 = 0; ni2 < 2; ni2++) {
                    const int brow = wn * 32 + ni2 * 16 + ((lane >> 4) & 1) * 8 + (lane & 7);
                    uint32_t r[4];
                    ldsm4(r, Bs + brow * 40 + bkc);
                    b[2*ni2    ][0] = r[0]; b[2*ni2    ][1] = r[1];
                    b[2*ni2 + 1][0] = r[2]; b[2*ni2 + 1][1] = r[3];
                }
            }
#pragma unroll
            for (int mi = 0; mi < 4; mi++)
#pragma unroll
                for (int ni = 0; ni < 4; ni++)
                    mma16(acc[mi][ni], a[mi], b[ni]);
        }
    }
    const int orow = m0 + wm * 64 + (lane >> 2);
    const int ocol = n0 + wn * 32 + (lane & 3) * 2;
#pragma unroll
    for (int mi = 0; mi < 4; mi++) {
        long ra = (long)(orow + mi * 16) * N;
        long rb = (long)(orow + mi * 16 + 8) * N;
#pragma unroll
        for (int ni = 0; ni < 4; ni++) {
            int n = ocol + ni * 8;
            C[ra + n] = acc[mi][ni][0]; C[ra + n + 1] = acc[mi][ni][1];
            C[rb + n] = acc[mi][ni][2]; C[rb + n + 1] = acc[mi][ni][3];
        }
    }
}

// ============================================================================
// fp16 AV GEMM (NN via trans-ldmatrix B), scatter epilogue to image layout
//   out_img <- sum_k S[z][m][k] * V[z][k][dd]   (S f32 converted, V half)
// ============================================================================
__global__ void __launch_bounds__(256) hgemm_av_kernel(
    const float* __restrict__ S, const __half* __restrict__ V, float* __restrict__ out,
    int n, int d, int lp, int c0)
{
    __shared__ __half As[128 * 40];
    __shared__ __half Bs[32 * 136];
    const int tid = threadIdx.x;
    const int lane = tid & 31, wid = tid >> 5;
    const int wm = wid & 1, wn = wid >> 1;
    const int z = blockIdx.z;
    S += (long)z * n * n;
    V += (long)z * n * d;
    const int n0 = blockIdx.x * 128;   // dd
    const int m0 = blockIdx.y * 128;   // token
    const int wr = tid >> 1, wkh = (tid & 1) * 16;
    const int bk = tid >> 3, bn0 = (tid & 7) * 16;

    float acc[4][4][4] = {};
    for (int k0 = 0; k0 < n; k0 += 32) {
        __syncthreads();
        {
            const float* sa = S + (long)(m0 + wr) * n + k0 + wkh;
            uint32_t* ad = (uint32_t*)(As + wr * 40 + wkh);
#pragma unroll
            for (int i4 = 0; i4 < 4; i4++) {
                float4 v = *(const float4*)(sa + i4 * 4);
                ad[i4*2 + 0] = pack_h2(v.x, v.y);
                ad[i4*2 + 1] = pack_h2(v.z, v.w);
            }
            const __half* sb = V + (long)(k0 + bk) * d + n0 + bn0;
            *(uint4*)(Bs + bk * 136 + bn0)     = *(const uint4*)sb;
            *(uint4*)(Bs + bk * 136 + bn0 + 8) = *(const uint4*)(sb + 8);
        }
        __syncthreads();
#pragma unroll
        for (int kstep = 0; kstep < 2; kstep++) {
            uint32_t a[4][4], b[4][2];
            {
                const int arow = wm * 64 + ((lane >> 3) & 1) * 8 + (lane & 7);
                const int akc  = kstep * 16 + (lane >> 4) * 8;
#pragma unroll
                for (int mi = 0; mi < 4; mi++)
                    ldsm4(a[mi], As + (arow + mi * 16) * 40 + akc);
            }
            {
                const int brow = kstep * 16 + (lane & 7) + ((lane >> 3) & 1) * 8;
#pragma unroll
                for (int ni2 = 0; ni2 < 2; ni2++) {
                    const int bcol = wn * 32 + ni2 * 16 + ((lane >> 4) & 1) * 8;
                    uint32_t r[4];
                    ldsm4t(r, Bs + brow * 136 + bcol);
                    b[2*ni2    ][0] = r[0]; b[2*ni2    ][1] = r[1];
                    b[2*ni2 + 1][0] = r[2]; b[2*ni2 + 1][1] = r[3];
                }
            }
#pragma unroll
            for (int mi = 0; mi < 4; mi++)
#pragma unroll
                for (int ni = 0; ni < 4; ni++)
                    mma16(acc[mi][ni], a[mi], b[ni]);
        }
    }

    const int lo = 6 - lp;
    const int orow = m0 + wm * 64 + (lane >> 2);
    const int ocol = n0 + wn * 32 + (lane & 3) * 2;
#pragma unroll
    for (int mi = 0; mi < 4; mi++) {
#pragma unroll
        for (int hf = 0; hf < 2; hf++) {
            const int m = orow + mi * 16 + hf * 8;
            const int t = m >> (2 * lo);
            const int r = m & ((1 << (2 * lo)) - 1);
            const int ohi = r >> lo, owi = r & ((1 << lo) - 1);
#pragma unroll
            for (int ni = 0; ni < 4; ni++) {
                const int col = ocol + ni * 8;
                const int cc = col >> (2 * lp);
                const int rr = col & ((1 << (2 * lp)) - 1);
                const int pi = rr >> lp, pj = rr & ((1 << lp) - 1);
                long dst = ((long)((z * 8 + t) * 256 + c0 + cc) << 12)
                         + (((ohi << lp) + pi) << 6) + (owi << lp) + pj;
                out[dst]     = acc[mi][ni][hf * 2];
                out[dst + 1] = acc[mi][ni][hf * 2 + 1];
            }
        }
    }
}

// ============================================================================
// SIMT 32x32 NT with split-K (P=32 scores): f32 accumulation of half inputs
// ============================================================================
__global__ void __launch_bounds__(256) smallnt_kernel(
    const __half* __restrict__ A, const __half* __restrict__ B, float* __restrict__ C,
    int nn, int K, int splitk)
{
    __shared__ float Qs[32][68];
    __shared__ float Ks[32][68];
    const int tid = threadIdx.x;
    const int z = blockIdx.z, bat = z / splitk, ks = z - bat * splitk;
    A += (long)bat * nn * K;
    B += (long)bat * nn * K;
    const int kchunk = K / splitk, kbeg = ks * kchunk;
    const int row = tid >> 3, seg = (tid & 7) * 8;
    const int i2 = (tid >> 4) * 2, j2 = (tid & 15) * 2;

    float acc00 = 0.f, acc01 = 0.f, acc10 = 0.f, acc11 = 0.f;
    for (int k0 = kbeg; k0 < kbeg + kchunk; k0 += 64) {
        __syncthreads();
        {
            uint4 qa = *(const uint4*)(A + (long)row * K + k0 + seg);
            const __half* hq = (const __half*)&qa;
            uint4 kb = *(const uint4*)(B + (long)row * K + k0 + seg);
            const __half* hk = (const __half*)&kb;
#pragma unroll
            for (int t = 0; t < 8; t++) {
                Qs[row][seg + t] = __half2float(hq[t]);
                Ks[row][seg + t] = __half2float(hk[t]);
            }
        }
        __syncthreads();
#pragma unroll 8
        for (int kk = 0; kk < 64; kk++) {
            float q0 = Qs[i2][kk], q1 = Qs[i2 + 1][kk];
            float k0v = Ks[j2][kk], k1v = Ks[j2 + 1][kk];
            acc00 += q0 * k0v; acc01 += q0 * k1v;
            acc10 += q1 * k0v; acc11 += q1 * k1v;
        }
    }
    float* Cz = C + (long)z * nn * nn;
    Cz[(long)i2 * nn + j2]           = acc00;
    Cz[(long)i2 * nn + j2 + 1]       = acc01;
    Cz[(long)(i2 + 1) * nn + j2]     = acc10;
    Cz[(long)(i2 + 1) * nn + j2 + 1] = acc11;
}

__global__ void reduce_splitk_kernel(const float* __restrict__ part, float* __restrict__ S,
                                     int per, int splitk)
{
    long idx = (long)blockIdx.x * 256 + threadIdx.x;
    int b = (int)(idx / per);
    int r = (int)(idx - (long)b * per);
    float s = 0.f;
    for (int ks = 0; ks < splitk; ks++)
        s += part[(long)(b * splitk + ks) * per + r];
    S[idx] = s;
}

// ===================== SIMT AV for P=32 (M=32, half V), scatter epilogue ==========
__global__ void __launch_bounds__(256) gemm_av32_kernel(
    const float* __restrict__ A, const __half* __restrict__ B, float* __restrict__ out,
    int n, int d, int lp, int c0)
{
    const int z = blockIdx.z;
    A += (long)z * n * n;
    B += (long)z * n * d;
    const int m0 = blockIdx.y * 64, n0 = blockIdx.x * 64;
    __shared__ __align__(16) float As[16][68];
    __shared__ __align__(16) float Bs[16][64];
    const int tid = threadIdx.x;
    const int tx = tid & 15, ty = tid >> 4;
    float acc[4][4] = {};
    for (int k0 = 0; k0 < n; k0 += 16) {
#pragma unroll
        for (int it = 0; it < 4; it++) {
            int id = tid + it * 256;
            int m = id >> 4, kk = id & 15;
            As[kk][m] = (m0 + m < n) ? A[(long)(m0 + m) * n + k0 + kk] : 0.f;
        }
#pragma unroll
        for (int it = 0; it < 4; it++) {
            int id = tid + it * 256;
            int kk = id >> 6, nnn = id & 63;
            Bs[kk][nnn] = __half2float(B[(long)(k0 + kk) * d + n0 + nnn]);
        }
        __syncthreads();
#pragma unroll
        for (int kk = 0; kk < 16; kk++) {
            float4 a4 = *(const float4*)&As[kk][ty * 4];
            float4 b4 = *(const float4*)&Bs[kk][tx * 4];
            float ar[4] = {a4.x, a4.y, a4.z, a4.w};
            float br[4] = {b4.x, b4.y, b4.z, b4.w};
#pragma unroll
            for (int i = 0; i < 4; i++)
#pragma unroll
                for (int j = 0; j < 4; j++)
                    acc[i][j] += ar[i] * br[j];
        }
        __syncthreads();
    }
    const int lo = 6 - lp, o = 1 << lo, P = 1 << lp;
#pragma unroll
    for (int i = 0; i < 4; i++) {
        int m = m0 + ty * 4 + i;
        if (m >= n) continue;
        int t = m >> (2 * lo);
        int r = m & ((1 << (2 * lo)) - 1);
        int ohi = r >> lo, owi = r & (o - 1);
        int col = n0 + tx * 4;
        int cc = col >> (2 * lp);
        int rr = col & (P * P - 1);
        int pi = rr >> lp, pj = rr & (P - 1);
        long dst = ((long)((z * 8 + t) * 256 + c0 + cc) << 12)
                 + (((ohi << lp) + pi) << 6) + (owi << lp) + pj;
#pragma unroll
        for (int j = 0; j < 4; j++)
            out[dst + j] = acc[i][j];
    }
}

// ===================== softmax (row-wise, scale folded in) ========================
__global__ void softmax_kernel(float* __restrict__ S, int n, float scale)
{
    __shared__ float buf[2048];
    __shared__ float red[256];
    const long row = blockIdx.x;
    float* p = S + row * (long)n;
    const int tid = threadIdx.x;
    float m = -1e30f;
    for (int i = tid; i < n; i += 256) { float v = p[i] * scale; buf[i] = v; m = fmaxf(m, v); }
    red[tid] = m; __syncthreads();
    for (int s = 128; s > 0; s >>= 1) { if (tid < s) red[tid] = fmaxf(red[tid], red[tid + s]); __syncthreads(); }
    m = red[0]; __syncthreads();
    float sum = 0.f;
    for (int i = tid; i < n; i += 256) { float e = expf(buf[i] - m); buf[i] = e; sum += e; }
    red[tid] = sum; __syncthreads();
    for (int s = 128; s > 0; s >>= 1) { if (tid < s) red[tid] += red[tid + s]; __syncthreads(); }
    float inv = 1.f / red[0];
    for (int i = tid; i < n; i += 256) p[i] = buf[i] * inv;
}

// ===================== launcher ===================================================
extern "C" void kernel_launch(void* const* d_in, const int* in_sizes, int n_in,
                              void* d_out, int out_size)
{
    const float* xs  = (const float*)d_in[0];
    const float* Wq  = (const float*)d_in[2];
    const float* bq  = (const float*)d_in[3];
    const float* Wk  = (const float*)d_in[4];
    const float* bk  = (const float*)d_in[5];
    const float* Wv  = (const float*)d_in[6];
    const float* bv  = (const float*)d_in[7];
    const float* Wl  = (const float*)d_in[8];
    const float* bl  = (const float*)d_in[9];
    const float* Wf1 = (const float*)d_in[10];
    const float* bf1 = (const float*)d_in[11];
    const float* Wf2 = (const float*)d_in[12];
    const float* bf2 = (const float*)d_in[13];
    float* out = (float*)d_out;

    __half *gQp, *gKp, *gVp;
    float *gS, *gPart, *gAtt, *gXs1, *gFf;
    cudaGetSymbolAddress((void**)&gQp,  g_Qp);
    cudaGetSymbolAddress((void**)&gKp,  g_Kp);
    cudaGetSymbolAddress((void**)&gVp,  g_Vp);
    cudaGetSymbolAddress((void**)&gS,   g_S);
    cudaGetSymbolAddress((void**)&gPart,g_part);
    cudaGetSymbolAddress((void**)&gAtt, g_att);
    cudaGetSymbolAddress((void**)&gXs1, g_xs1);
    cudaGetSymbolAddress((void**)&gFf,  g_ff);

    dim3 blk(256);
    dim3 cgrid(NIMG * 32, 2);

    // QKV projections -> patchified half buffers (bias fused)
    hconv_kernel<<<cgrid, blk>>>(xs, Wq, bq, nullptr, nullptr, gQp, 1, 1, 0, 0, 1);
    hconv_kernel<<<cgrid, blk>>>(xs, Wk, bk, nullptr, nullptr, gKp, 1, 1, 0, 0, 1);
    hconv_kernel<<<cgrid, blk>>>(xs, Wv, bv, nullptr, nullptr, gVp, 1, 1, 0, 0, 1);

    // ---- P=32 (n=32, d=65536): SIMT small-NT + SIMT AV ----
    {
        const int n = 32, d = 65536, splitk = 128;
        smallnt_kernel<<<dim3(1, 1, 2 * splitk), blk>>>(gQp, gKp, gPart, n, d, splitk);
        reduce_splitk_kernel<<<(2 * n * n) / 256, blk>>>(gPart, gS, n * n, splitk);
        softmax_kernel<<<2 * n, blk>>>(gS, n, 1.0f / 256.0f);
        gemm_av32_kernel<<<dim3(d / 64, 1, 2), blk>>>(gS, gVp, gAtt, n, d, 5, 0);
    }
    // ---- P=16 (n=128, d=16384): fp16 mma split-K ----
    {
        const int n = 128, d = 16384, splitk = 64;
        const long soff = 4194304;
        hgemm_nt_kernel<<<dim3(1, 1, 2 * splitk), blk>>>(
            gQp + soff, gKp + soff, gPart, n, d, splitk, (long)n * d, (long)n * n);
        reduce_splitk_kernel<<<(2 * n * n) / 256, blk>>>(gPart, gS, n * n, splitk);
        softmax_kernel<<<2 * n, blk>>>(gS, n, 1.0f / 128.0f);
        hgemm_av_kernel<<<dim3(d / 128, n / 128, 2), blk>>>(gS, gVp + soff, gAtt, n, d, 4, 64);
    }
    // ---- P=8 (n=512, d=4096): fp16 mma split-K ----
    {
        const int n = 512, d = 4096, splitk = 8;
        const long soff = 2L * 4194304;
        hgemm_nt_kernel<<<dim3(n / 128, n / 128, 2 * splitk), blk>>>(
            gQp + soff, gKp + soff, gPart, n, d, splitk, (long)n * d, (long)n * n);
        reduce_splitk_kernel<<<(2 * n * n) / 256, blk>>>(gPart, gS, n * n, splitk);
        softmax_kernel<<<2 * n, blk>>>(gS, n, 1.0f / 64.0f);
        hgemm_av_kernel<<<dim3(d / 128, n / 128, 2), blk>>>(gS, gVp + soff, gAtt, n, d, 3, 128);
    }
    // ---- P=4 (n=2048, d=1024): fp16 mma direct ----
    {
        const int n = 2048, d = 1024;
        const long soff = 3L * 4194304;
        hgemm_nt_kernel<<<dim3(n / 128, n / 128, 2), blk>>>(
            gQp + soff, gKp + soff, gS, n, d, 1, (long)n * d, (long)n * n);
        softmax_kernel<<<2 * n, blk>>>(gS, n, 1.0f / 32.0f);
        hgemm_av_kernel<<<dim3(d / 128, n / 128, 2), blk>>>(gS, gVp + soff, gAtt, n, d, 2, 192);
    }

    // convs (bias + leaky + residual fused)
    hconv_kernel<<<cgrid, blk>>>(gAtt, Wl, bl, xs,   gXs1, nullptr, 3, 1, 1, 1, 0);
    hconv_kernel<<<cgrid, blk>>>(gXs1, Wf1, bf1, xs, gFf,  nullptr, 3, 1, 1, 0, 0);
    hconv_kernel<<<cgrid, blk>>>(gFf,  Wf2, bf2, gXs1, out, nullptr, 3, 2, 1, 1, 0);
}

// round 6
// speedup vs baseline: 5.7409x; 1.0012x over previous
#include <cuda_runtime.h>
#include <cuda_fp16.h>
#include <math.h>
#include <stdint.h>

#define NIMG 16
#define CCH 256
#define NPIX 4096            // 64*64

// ---- scratch (static device globals; no allocation) ----
__device__ __half g_Qp[16777216];
__device__ __half g_Kp[16777216];
__device__ __half g_Vp[16777216];
__device__ float  g_S[2*2048*2048];
__device__ float  g_part[8388608];
__device__ float  g_xs1[NIMG*CCH*NPIX];
__device__ __half g_xsh [NIMG*CCH*NPIX];
__device__ __half g_atth[NIMG*CCH*NPIX];
__device__ __half g_xs1h[NIMG*CCH*NPIX];
__device__ __half g_ffh [NIMG*CCH*NPIX];
__device__ __half g_Wqh[65536], g_Wkh[65536], g_Wvh[65536];
__device__ __half g_Wlh[589824], g_Wf1h[589824], g_Wf2h[589824];

// ============================================================================
// helpers
// ============================================================================
__device__ __forceinline__ void mma16(float* d, const uint32_t* a, const uint32_t* b) {
    asm volatile(
        "mma.sync.aligned.m16n8k16.row.col.f32.f16.f16.f32 "
        "{%0,%1,%2,%3}, {%4,%5,%6,%7}, {%8,%9}, {%0,%1,%2,%3};"
        : "+f"(d[0]), "+f"(d[1]), "+f"(d[2]), "+f"(d[3])
        : "r"(a[0]), "r"(a[1]), "r"(a[2]), "r"(a[3]), "r"(b[0]), "r"(b[1]));
}

__device__ __forceinline__ void ldsm4(uint32_t* r, const void* p) {
    uint32_t addr = (uint32_t)__cvta_generic_to_shared(p);
    asm volatile("ldmatrix.sync.aligned.m8n8.x4.shared.b16 {%0,%1,%2,%3}, [%4];"
        : "=r"(r[0]), "=r"(r[1]), "=r"(r[2]), "=r"(r[3]) : "r"(addr));
}

__device__ __forceinline__ void ldsm4t(uint32_t* r, const void* p) {
    uint32_t addr = (uint32_t)__cvta_generic_to_shared(p);
    asm volatile("ldmatrix.sync.aligned.m8n8.x4.trans.shared.b16 {%0,%1,%2,%3}, [%4];"
        : "=r"(r[0]), "=r"(r[1]), "=r"(r[2]), "=r"(r[3]) : "r"(addr));
}

__device__ __forceinline__ uint32_t pack_h2(float a, float b) {
    __half2 h = __floats2half2_rn(a, b);
    return *(uint32_t*)&h;
}

// f32 -> f16 bulk convert (exact multiples of 1024 elems)
__global__ void f2h_kernel(const float* __restrict__ src, __half* __restrict__ dst) {
    long i = ((long)blockIdx.x * 256 + threadIdx.x) * 4;
    float4 v = *(const float4*)(src + i);
    *(uint32_t*)(dst + i)     = pack_h2(v.x, v.y);
    *(uint32_t*)(dst + i + 2) = pack_h2(v.z, v.w);
}

// scatter index into patchified buffer: scale = oc>>6
__device__ __forceinline__ long pat_index(int img, int oc, int pix) {
    int s  = oc >> 6, cc = oc & 63;
    int lp = 5 - s;
    int lo = 1 + s;
    int Pm = (1 << lp) - 1;
    int y = pix >> 6, x = pix & 63;
    int ohi = y >> lp, pi = y & Pm, owi = x >> lp, pj = x & Pm;
    int t = img & 7, b = img >> 3;
    int nn = (t << (2*lo)) + (ohi << lo) + owi;
    int dd = (cc << (2*lp)) + (pi << lp) + pj;
    return (long)s * 4194304 + (long)b * 2097152 + (long)nn * (64 << (2*lp)) + dd;
}

// ============================================================================
// fp16 mma conv / projection, pipelined double-buffered SMEM, half I/O
//   outh_pat != null : QKV mode, scatter patchified half (bias only)
//   else: bias + (leaky) + (residual f32); writes out (f32, opt) and outh_img (half, opt)
// ============================================================================
__global__ void __launch_bounds__(256) hconv_kernel(
    const __half* __restrict__ in, const __half* __restrict__ Wt,
    const float* __restrict__ bias, const float* __restrict__ res,
    float* __restrict__ out, __half* __restrict__ outh_img, __half* __restrict__ outh_pat,
    int ks, int dil, int do_leaky, int addres)
{
    __shared__ __half As[2][128 * 40];
    __shared__ __half Bs[2][128 * 40];
    const int tid = threadIdx.x;
    const int lane = tid & 31, wid = tid >> 5;
    const int wm = wid & 1, wn = wid >> 1;
    const int K = CCH * ks * ks;
    const int nch = K / 32;
    const int img = blockIdx.x >> 5;
    const int p0 = (blockIdx.x & 31) * 128;
    const int m0 = blockIdx.y * 128;
    const __half* inimg = in + (long)img * CCH * NPIX;

    const int wr  = tid >> 1;
    const int wkh = (tid & 1) * 16;
    const int py = (p0 + wr) >> 6, px = (p0 + wr) & 63;

    float acc[4][4][4] = {};
    uint4 aw0, aw1;
    uint32_t bw[8];

#define GATHER(K0)                                                              \
    {                                                                           \
        const __half* asrc = Wt + (long)(m0 + wr) * K + (K0) + wkh;             \
        aw0 = *(const uint4*)asrc;                                              \
        aw1 = *(const uint4*)(asrc + 8);                                        \
        if (ks == 1) {                                                          \
            _Pragma("unroll")                                                   \
            for (int i2 = 0; i2 < 8; i2++) {                                    \
                uint32_t lo = *(const uint16_t*)&inimg[((K0) + wkh + 2*i2    ) * NPIX + p0 + wr]; \
                uint32_t hi = *(const uint16_t*)&inimg[((K0) + wkh + 2*i2 + 1) * NPIX + p0 + wr]; \
                bw[i2] = lo | (hi << 16);                                       \
            }                                                                   \
        } else {                                                                \
            uint32_t hv[16];                                                    \
            _Pragma("unroll")                                                   \
            for (int i = 0; i < 16; i++) {                                      \
                int k = (K0) + wkh + i;                                         \
                int c = k / 9;                                                  \
                int tap = k - c * 9;                                            \
                int ky = tap / 3, kx = tap - ky * 3;                            \
                int sy = py + (ky - 1) * dil;                                   \
                int sx = px + (kx - 1) * dil;                                   \
                uint32_t v = 0;                                                 \
                if ((unsigned)sy < 64u && (unsigned)sx < 64u)                   \
                    v = *(const uint16_t*)&inimg[(c << 12) + (sy << 6) + sx];   \
                hv[i] = v;                                                      \
            }                                                                   \
            _Pragma("unroll")                                                   \
            for (int i2 = 0; i2 < 8; i2++)                                      \
                bw[i2] = hv[2*i2] | (hv[2*i2 + 1] << 16);                       \
        }                                                                       \
    }

#define STORE(BUF)                                                              \
    {                                                                           \
        *(uint4*)(As[BUF] + wr * 40 + wkh)     = aw0;                           \
        *(uint4*)(As[BUF] + wr * 40 + wkh + 8) = aw1;                           \
        uint32_t* bd = (uint32_t*)(Bs[BUF] + wr * 40 + wkh);                    \
        _Pragma("unroll")                                                       \
        for (int i2 = 0; i2 < 8; i2++) bd[i2] = bw[i2];                         \
    }

    GATHER(0);
    STORE(0);

    for (int kc = 0; kc < nch; kc++) {
        __syncthreads();
        const int cur = kc & 1;
        const bool pre = (kc + 1 < nch);
        if (pre) GATHER((kc + 1) * 32);

#pragma unroll
        for (int kstep = 0; kstep < 2; kstep++) {
            uint32_t a[4][4], b[4][2];
            {
                const int arow = wm * 64 + ((lane >> 3) & 1) * 8 + (lane & 7);
                const int akc  = kstep * 16 + (lane >> 4) * 8;
#pragma unroll
                for (int mi = 0; mi < 4; mi++)
                    ldsm4(a[mi], As[cur] + (arow + mi * 16) * 40 + akc);
            }
            {
                const int bkc = kstep * 16 + ((lane >> 3) & 1) * 8;
#pragma unroll
                for (int ni2 = 0; ni2 < 2; ni2++) {
                    const int brow = wn * 32 + ni2 * 16 + ((lane >> 4) & 1) * 8 + (lane & 7);
                    uint32_t r[4];
                    ldsm4(r, Bs[cur] + brow * 40 + bkc);
                    b[2*ni2    ][0] = r[0]; b[2*ni2    ][1] = r[1];
                    b[2*ni2 + 1][0] = r[2]; b[2*ni2 + 1][1] = r[3];
                }
            }
#pragma unroll
            for (int mi = 0; mi < 4; mi++)
#pragma unroll
                for (int ni = 0; ni < 4; ni++)
                    mma16(acc[mi][ni], a[mi], b[ni]);
        }
        if (pre) STORE(cur ^ 1);
    }
#undef GATHER
#undef STORE

    const int orow = m0 + wm * 64 + (lane >> 2);
    const int ocol = p0 + wn * 32 + (lane & 3) * 2;

    if (outh_pat) {
#pragma unroll
        for (int mi = 0; mi < 4; mi++) {
            const int oca = orow + mi * 16, ocb = oca + 8;
            const float ba = bias[oca], bb = bias[ocb];
#pragma unroll
            for (int ni = 0; ni < 4; ni++) {
                const int n = ocol + ni * 8;
                long ia = pat_index(img, oca, n);
                long ib = pat_index(img, ocb, n);
                *(__half2*)(outh_pat + ia) = __floats2half2_rn(acc[mi][ni][0] + ba, acc[mi][ni][1] + ba);
                *(__half2*)(outh_pat + ib) = __floats2half2_rn(acc[mi][ni][2] + bb, acc[mi][ni][3] + bb);
            }
        }
    } else {
#pragma unroll
        for (int mi = 0; mi < 4; mi++) {
            const int oca = orow + mi * 16;
            const int ocb = oca + 8;
            const float ba = bias[oca], bb = bias[ocb];
#pragma unroll
            for (int ni = 0; ni < 4; ni++) {
                const int n = ocol + ni * 8;
                long ia = ((long)img * 256 + oca) * NPIX + n;
                long ib = ((long)img * 256 + ocb) * NPIX + n;
                float v0 = acc[mi][ni][0] + ba, v1 = acc[mi][ni][1] + ba;
                float v2 = acc[mi][ni][2] + bb, v3 = acc[mi][ni][3] + bb;
                if (do_leaky) {
                    v0 = (v0 > 0.f) ? v0 : 0.2f * v0;
                    v1 = (v1 > 0.f) ? v1 : 0.2f * v1;
                    v2 = (v2 > 0.f) ? v2 : 0.2f * v2;
                    v3 = (v3 > 0.f) ? v3 : 0.2f * v3;
                }
                if (addres) {
                    v0 += res[ia]; v1 += res[ia + 1];
                    v2 += res[ib]; v3 += res[ib + 1];
                }
                if (out) {
                    out[ia] = v0; out[ia + 1] = v1;
                    out[ib] = v2; out[ib + 1] = v3;
                }
                if (outh_img) {
                    *(__half2*)(outh_img + ia) = __floats2half2_rn(v0, v1);
                    *(__half2*)(outh_img + ib) = __floats2half2_rn(v2, v3);
                }
            }
        }
    }
}

// ============================================================================
// fp16 NT GEMM with deterministic split-K (scores), f32 out
// ============================================================================
__global__ void __launch_bounds__(256) hgemm_nt_kernel(
    const __half* __restrict__ A, const __half* __restrict__ B, float* __restrict__ C,
    int N, int K, int splitk, long sAB, long sC)
{
    __shared__ __half As[128 * 40];
    __shared__ __half Bs[128 * 40];
    const int tid = threadIdx.x;
    const int lane = tid & 31, wid = tid >> 5;
    const int wm = wid & 1, wn = wid >> 1;
    const int n0 = blockIdx.x * 128, m0 = blockIdx.y * 128;
    const int z = blockIdx.z, bat = z / splitk, ks = z - bat * splitk;
    A += (long)bat * sAB;
    B += (long)bat * sAB;
    C += (long)z * sC;
    const int kchunk = K / splitk, kbeg = ks * kchunk;
    const int wr = tid >> 1, wkh = (tid & 1) * 16;

    float acc[4][4][4] = {};
    for (int k0 = kbeg; k0 < kbeg + kchunk; k0 += 32) {
        __syncthreads();
        {
            const __half* sa = A + (long)(m0 + wr) * K + k0 + wkh;
            const __half* sb = B + (long)(n0 + wr) * K + k0 + wkh;
            *(uint4*)(As + wr * 40 + wkh)     = *(const uint4*)sa;
            *(uint4*)(As + wr * 40 + wkh + 8) = *(const uint4*)(sa + 8);
            *(uint4*)(Bs + wr * 40 + wkh)     = *(const uint4*)sb;
            *(uint4*)(Bs + wr * 40 + wkh + 8) = *(const uint4*)(sb + 8);
        }
        __syncthreads();
#pragma unroll
        for (int kstep = 0; kstep < 2; kstep++) {
            uint32_t a[4][4], b[4][2];
            {
                const int arow = wm * 64 + ((lane >> 3) & 1) * 8 + (lane & 7);
                const int akc  = kstep * 16 + (lane >> 4) * 8;
#pragma unroll
                for (int mi = 0; mi < 4; mi++)
                    ldsm4(a[mi], As + (arow + mi * 16) * 40 + akc);
            }
            {
                const int bkc = kstep * 16 + ((lane >> 3) & 1) * 8;
#pragma unroll
                for (int ni2 = 0; ni2 < 2; ni2++) {
                    const int brow = wn * 32 + ni2 * 16 + ((lane >> 4) & 1) * 8 + (lane & 7);
                    uint32_t r[4];
                    ldsm4(r, Bs + brow * 40 + bkc);
                    b[2*ni2    ][0] = r[0]; b[2*ni2    ][1] = r[1];
                    b[2*ni2 + 1][0] = r[2]; b[2*ni2 + 1][1] = r[3];
                }
            }
#pragma unroll
            for (int mi = 0; mi < 4; mi++)
#pragma unroll
                for (int ni = 0; ni < 4; ni++)
                    mma16(acc[mi][ni], a[mi], b[ni]);
        }
    }
    const int orow = m0 + wm * 64 + (lane >> 2);
    const int ocol = n0 + wn * 32 + (lane & 3) * 2;
#pragma unroll
    for (int mi = 0; mi < 4; mi++) {
        long ra = (long)(orow + mi * 16) * N;
        long rb = (long)(orow + mi * 16 + 8) * N;
#pragma unroll
        for (int ni = 0; ni < 4; ni++) {
            int n = ocol + ni * 8;
            C[ra + n] = acc[mi][ni][0]; C[ra + n + 1] = acc[mi][ni][1];
            C[rb + n] = acc[mi][ni][2]; C[rb + n + 1] = acc[mi][ni][3];
        }
    }
}

// ============================================================================
// fp16 AV GEMM (NN via trans-ldmatrix B), scatter epilogue -> half image
// ============================================================================
__global__ void __launch_bounds__(256) hgemm_av_kernel(
    const float* __restrict__ S, const __half* __restrict__ V, __half* __restrict__ out,
    int n, int d, int lp, int c0)
{
    __shared__ __half As[128 * 40];
    __shared__ __half Bs[32 * 136];
    const int tid = threadIdx.x;
    const int lane = tid & 31, wid = tid >> 5;
    const int wm = wid & 1, wn = wid >> 1;
    const int z = blockIdx.z;
    S += (long)z * n * n;
    V += (long)z * n * d;
    const int n0 = blockIdx.x * 128;
    const int m0 = blockIdx.y * 128;
    const int wr = tid >> 1, wkh = (tid & 1) * 16;
    const int bk = tid >> 3, bn0 = (tid & 7) * 16;

    float acc[4][4][4] = {};
    for (int k0 = 0; k0 < n; k0 += 32) {
        __syncthreads();
        {
            const float* sa = S + (long)(m0 + wr) * n + k0 + wkh;
            uint32_t* ad = (uint32_t*)(As + wr * 40 + wkh);
#pragma unroll
            for (int i4 = 0; i4 < 4; i4++) {
                float4 v = *(const float4*)(sa + i4 * 4);
                ad[i4*2 + 0] = pack_h2(v.x, v.y);
                ad[i4*2 + 1] = pack_h2(v.z, v.w);
            }
            const __half* sb = V + (long)(k0 + bk) * d + n0 + bn0;
            *(uint4*)(Bs + bk * 136 + bn0)     = *(const uint4*)sb;
            *(uint4*)(Bs + bk * 136 + bn0 + 8) = *(const uint4*)(sb + 8);
        }
        __syncthreads();
#pragma unroll
        for (int kstep = 0; kstep < 2; kstep++) {
            uint32_t a[4][4], b[4][2];
            {
                const int arow = wm * 64 + ((lane >> 3) & 1) * 8 + (lane & 7);
                const int akc  = kstep * 16 + (lane >> 4) * 8;
#pragma unroll
                for (int mi = 0; mi < 4; mi++)
                    ldsm4(a[mi], As + (arow + mi * 16) * 40 + akc);
            }
            {
                const int brow = kstep * 16 + (lane & 7) + ((lane >> 3) & 1) * 8;
#pragma unroll
                for (int ni2 = 0; ni2 < 2; ni2++) {
                    const int bcol = wn * 32 + ni2 * 16 + ((lane >> 4) & 1) * 8;
                    uint32_t r[4];
                    ldsm4t(r, Bs + brow * 136 + bcol);
                    b[2*ni2    ][0] = r[0]; b[2*ni2    ][1] = r[1];
                    b[2*ni2 + 1][0] = r[2]; b[2*ni2 + 1][1] = r[3];
                }
            }
#pragma unroll
            for (int mi = 0; mi < 4; mi++)
#pragma unroll
                for (int ni = 0; ni < 4; ni++)
                    mma16(acc[mi][ni], a[mi], b[ni]);
        }
    }

    const int lo = 6 - lp;
    const int orow = m0 + wm * 64 + (lane >> 2);
    const int ocol = n0 + wn * 32 + (lane & 3) * 2;
#pragma unroll
    for (int mi = 0; mi < 4; mi++) {
#pragma unroll
        for (int hf = 0; hf < 2; hf++) {
            const int m = orow + mi * 16 + hf * 8;
            const int t = m >> (2 * lo);
            const int r = m & ((1 << (2 * lo)) - 1);
            const int ohi = r >> lo, owi = r & ((1 << lo) - 1);
#pragma unroll
            for (int ni = 0; ni < 4; ni++) {
                const int col = ocol + ni * 8;
                const int cc = col >> (2 * lp);
                const int rr = col & ((1 << (2 * lp)) - 1);
                const int pi = rr >> lp, pj = rr & ((1 << lp) - 1);
                long dst = ((long)((z * 8 + t) * 256 + c0 + cc) << 12)
                         + (((ohi << lp) + pi) << 6) + (owi << lp) + pj;
                *(__half2*)(out + dst) = __floats2half2_rn(acc[mi][ni][hf*2], acc[mi][ni][hf*2 + 1]);
            }
        }
    }
}

// ============================================================================
// fp16 mma 32x32 NT split-K (P=32 scores): 2 warps, cross-warp smem reduce
// ============================================================================
__global__ void __launch_bounds__(64) hgemm32_kernel(
    const __half* __restrict__ A, const __half* __restrict__ B, float* __restrict__ C,
    int K, int splitk)
{
    __shared__ __half Qs[32 * 136];
    __shared__ __half Ks[32 * 136];
    __shared__ float buf[32][33];
    const int tid = threadIdx.x;
    const int lane = tid & 31, wrp = tid >> 5;
    const int z = blockIdx.z, bat = z / splitk, ks = z - bat * splitk;
    A += (long)bat * 32 * K;
    B += (long)bat * 32 * K;
    const int kchunk = K / splitk, kbeg = ks * kchunk;

    float acc[2][4][4] = {};
    for (int k0 = kbeg; k0 < kbeg + kchunk; k0 += 128) {
        __syncthreads();
#pragma unroll
        for (int i = 0; i < 8; i++) {
            int u = i * 64 + tid;                   // uint4 id 0..511
            int row = u >> 4, seg = (u & 15) * 8;
            *(uint4*)(Qs + row * 136 + seg) = *(const uint4*)(A + (long)row * K + k0 + seg);
            *(uint4*)(Ks + row * 136 + seg) = *(const uint4*)(B + (long)row * K + k0 + seg);
        }
        __syncthreads();
        for (int s = wrp; s < 8; s += 2) {
            const int kc = s * 16;
            uint32_t a[2][4], b[4][2];
            {
                const int arow = ((lane >> 3) & 1) * 8 + (lane & 7);
                const int akc  = kc + (lane >> 4) * 8;
                ldsm4(a[0], Qs + arow * 136 + akc);
                ldsm4(a[1], Qs + (arow + 16) * 136 + akc);
            }
            {
                const int bkc = kc + ((lane >> 3) & 1) * 8;
#pragma unroll
                for (int ni2 = 0; ni2 < 2; ni2++) {
                    const int brow = ni2 * 16 + ((lane >> 4) & 1) * 8 + (lane & 7);
                    uint32_t r[4];
                    ldsm4(r, Ks + brow * 136 + bkc);
                    b[2*ni2    ][0] = r[0]; b[2*ni2    ][1] = r[1];
                    b[2*ni2 + 1][0] = r[2]; b[2*ni2 + 1][1] = r[3];
                }
            }
#pragma unroll
            for (int mi = 0; mi < 2; mi++)
#pragma unroll
                for (int ni = 0; ni < 4; ni++)
                    mma16(acc[mi][ni], a[mi], b[ni]);
        }
    }

    // cross-warp reduce
    const int rr = lane >> 2, cc = (lane & 3) * 2;
    if (wrp == 0) {
#pragma unroll
        for (int mi = 0; mi < 2; mi++)
#pragma unroll
            for (int ni = 0; ni < 4; ni++) {
                buf[mi*16 + rr    ][ni*8 + cc]     = acc[mi][ni][0];
                buf[mi*16 + rr    ][ni*8 + cc + 1] = acc[mi][ni][1];
                buf[mi*16 + rr + 8][ni*8 + cc]     = acc[mi][ni][2];
                buf[mi*16 + rr + 8][ni*8 + cc + 1] = acc[mi][ni][3];
            }
    }
    __syncthreads();
    if (wrp == 1) {
#pragma unroll
        for (int mi = 0; mi < 2; mi++)
#pragma unroll
            for (int ni = 0; ni < 4; ni++) {
                buf[mi*16 + rr    ][ni*8 + cc]     += acc[mi][ni][0];
                buf[mi*16 + rr    ][ni*8 + cc + 1] += acc[mi][ni][1];
                buf[mi*16 + rr + 8][ni*8 + cc]     += acc[mi][ni][2];
                buf[mi*16 + rr + 8][ni*8 + cc + 1] += acc[mi][ni][3];
            }
    }
    __syncthreads();
    float* Cz = C + (long)z * 1024;
    for (int i = tid; i < 1024; i += 64)
        Cz[i] = buf[i >> 5][i & 31];
}

__global__ void reduce_splitk_kernel(const float* __restrict__ part, float* __restrict__ S,
                                     int per, int splitk)
{
    long idx = (long)blockIdx.x * 256 + threadIdx.x;
    int b = (int)(idx / per);
    int r = (int)(idx - (long)b * per);
    float s = 0.f;
    for (int ks = 0; ks < splitk; ks++)
        s += part[(long)(b * splitk + ks) * per + r];
    S[idx] = s;
}

// ===================== SIMT AV for P=32 (M=32, half V), half out ==================
__global__ void __launch_bounds__(256) gemm_av32_kernel(
    const float* __restrict__ A, const __half* __restrict__ B, __half* __restrict__ out,
    int n, int d, int lp, int c0)
{
    const int z = blockIdx.z;
    A += (long)z * n * n;
    B += (long)z * n * d;
    const int m0 = blockIdx.y * 64, n0 = blockIdx.x * 64;
    __shared__ __align__(16) float As[16][68];
    __shared__ __align__(16) float Bs[16][64];
    const int tid = threadIdx.x;
    const int tx = tid & 15, ty = tid >> 4;
    float acc[4][4] = {};
    for (int k0 = 0; k0 < n; k0 += 16) {
#pragma unroll
        for (int it = 0; it < 4; it++) {
            int id = tid + it * 256;
            int m = id >> 4, kk = id & 15;
            As[kk][m] = (m0 + m < n) ? A[(long)(m0 + m) * n + k0 + kk] : 0.f;
        }
#pragma unroll
        for (int it = 0; it < 4; it++) {
            int id = tid + it * 256;
            int kk = id >> 6, nnn = id & 63;
            Bs[kk][nnn] = __half2float(B[(long)(k0 + kk) * d + n0 + nnn]);
        }
        __syncthreads();
#pragma unroll
        for (int kk = 0; kk < 16; kk++) {
            float4 a4 = *(const float4*)&As[kk][ty * 4];
            float4 b4 = *(const float4*)&Bs[kk][tx * 4];
            float ar[4] = {a4.x, a4.y, a4.z, a4.w};
            float br[4] = {b4.x, b4.y, b4.z, b4.w};
#pragma unroll
            for (int i = 0; i < 4; i++)
#pragma unroll
                for (int j = 0; j < 4; j++)
                    acc[i][j] += ar[i] * br[j];
        }
        __syncthreads();
    }
    const int lo = 6 - lp, o = 1 << lo, P = 1 << lp;
#pragma unroll
    for (int i = 0; i < 4; i++) {
        int m = m0 + ty * 4 + i;
        if (m >= n) continue;
        int t = m >> (2 * lo);
        int r = m & ((1 << (2 * lo)) - 1);
        int ohi = r >> lo, owi = r & (o - 1);
        int col = n0 + tx * 4;
        int cc = col >> (2 * lp);
        int rr = col & (P * P - 1);
        int pi = rr >> lp, pj = rr & (P - 1);
        long dst = ((long)((z * 8 + t) * 256 + c0 + cc) << 12)
                 + (((ohi << lp) + pi) << 6) + (owi << lp) + pj;
        *(__half2*)(out + dst)     = __floats2half2_rn(acc[i][0], acc[i][1]);
        *(__half2*)(out + dst + 2) = __floats2half2_rn(acc[i][2], acc[i][3]);
    }
}

// ===================== softmax (row-wise, scale folded in) ========================
__global__ void softmax_kernel(float* __restrict__ S, int n, float scale)
{
    __shared__ float buf[2048];
    __shared__ float red[256];
    const long row = blockIdx.x;
    float* p = S + row * (long)n;
    const int tid = threadIdx.x;
    float m = -1e30f;
    for (int i = tid; i < n; i += 256) { float v = p[i] * scale; buf[i] = v; m = fmaxf(m, v); }
    red[tid] = m; __syncthreads();
    for (int s = 128; s > 0; s >>= 1) { if (tid < s) red[tid] = fmaxf(red[tid], red[tid + s]); __syncthreads(); }
    m = red[0]; __syncthreads();
    float sum = 0.f;
    for (int i = tid; i < n; i += 256) { float e = expf(buf[i] - m); buf[i] = e; sum += e; }
    red[tid] = sum; __syncthreads();
    for (int s = 128; s > 0; s >>= 1) { if (tid < s) red[tid] += red[tid + s]; __syncthreads(); }
    float inv = 1.f / red[0];
    for (int i = tid; i < n; i += 256) p[i] = buf[i] * inv;
}

// ===================== launcher ===================================================
extern "C" void kernel_launch(void* const* d_in, const int* in_sizes, int n_in,
                              void* d_out, int out_size)
{
    const float* xs  = (const float*)d_in[0];
    const float* Wq  = (const float*)d_in[2];
    const float* bq  = (const float*)d_in[3];
    const float* Wk  = (const float*)d_in[4];
    const float* bk  = (const float*)d_in[5];
    const float* Wv  = (const float*)d_in[6];
    const float* bv  = (const float*)d_in[7];
    const float* Wl  = (const float*)d_in[8];
    const float* bl  = (const float*)d_in[9];
    const float* Wf1 = (const float*)d_in[10];
    const float* bf1 = (const float*)d_in[11];
    const float* Wf2 = (const float*)d_in[12];
    const float* bf2 = (const float*)d_in[13];
    float* out = (float*)d_out;

    __half *gQp, *gKp, *gVp, *gXsh, *gAtth, *gXs1h, *gFfh;
    __half *gWqh, *gWkh, *gWvh, *gWlh, *gWf1h, *gWf2h;
    float *gS, *gPart, *gXs1;
    cudaGetSymbolAddress((void**)&gQp,   g_Qp);
    cudaGetSymbolAddress((void**)&gKp,   g_Kp);
    cudaGetSymbolAddress((void**)&gVp,   g_Vp);
    cudaGetSymbolAddress((void**)&gS,    g_S);
    cudaGetSymbolAddress((void**)&gPart, g_part);
    cudaGetSymbolAddress((void**)&gXs1,  g_xs1);
    cudaGetSymbolAddress((void**)&gXsh,  g_xsh);
    cudaGetSymbolAddress((void**)&gAtth, g_atth);
    cudaGetSymbolAddress((void**)&gXs1h, g_xs1h);
    cudaGetSymbolAddress((void**)&gFfh,  g_ffh);
    cudaGetSymbolAddress((void**)&gWqh,  g_Wqh);
    cudaGetSymbolAddress((void**)&gWkh,  g_Wkh);
    cudaGetSymbolAddress((void**)&gWvh,  g_Wvh);
    cudaGetSymbolAddress((void**)&gWlh,  g_Wlh);
    cudaGetSymbolAddress((void**)&gWf1h, g_Wf1h);
    cudaGetSymbolAddress((void**)&gWf2h, g_Wf2h);

    dim3 blk(256);
    dim3 cgrid(NIMG * 32, 2);

    // pre-convert inputs + weights to half
    f2h_kernel<<<16384, blk>>>(xs,  gXsh);
    f2h_kernel<<<64,    blk>>>(Wq,  gWqh);
    f2h_kernel<<<64,    blk>>>(Wk,  gWkh);
    f2h_kernel<<<64,    blk>>>(Wv,  gWvh);
    f2h_kernel<<<576,   blk>>>(Wl,  gWlh);
    f2h_kernel<<<576,   blk>>>(Wf1, gWf1h);
    f2h_kernel<<<576,   blk>>>(Wf2, gWf2h);

    // QKV projections -> patchified half buffers (bias fused)
    hconv_kernel<<<cgrid, blk>>>(gXsh, gWqh, bq, nullptr, nullptr, nullptr, gQp, 1, 1, 0, 0);
    hconv_kernel<<<cgrid, blk>>>(gXsh, gWkh, bk, nullptr, nullptr, nullptr, gKp, 1, 1, 0, 0);
    hconv_kernel<<<cgrid, blk>>>(gXsh, gWvh, bv, nullptr, nullptr, nullptr, gVp, 1, 1, 0, 0);

    // ---- P=32 (n=32, d=65536) ----
    {
        const int n = 32, d = 65536, splitk = 256;
        hgemm32_kernel<<<dim3(1, 1, 2 * splitk), 64>>>(gQp, gKp, gPart, d, splitk);
        reduce_splitk_kernel<<<(2 * n * n) / 256, blk>>>(gPart, gS, n * n, splitk);
        softmax_kernel<<<2 * n, blk>>>(gS, n, 1.0f / 256.0f);
        gemm_av32_kernel<<<dim3(d / 64, 1, 2), blk>>>(gS, gVp, gAtth, n, d, 5, 0);
    }
    // ---- P=16 (n=128, d=16384) ----
    {
        const int n = 128, d = 16384, splitk = 64;
        const long soff = 4194304;
        hgemm_nt_kernel<<<dim3(1, 1, 2 * splitk), blk>>>(
            gQp + soff, gKp + soff, gPart, n, d, splitk, (long)n * d, (long)n * n);
        reduce_splitk_kernel<<<(2 * n * n) / 256, blk>>>(gPart, gS, n * n, splitk);
        softmax_kernel<<<2 * n, blk>>>(gS, n, 1.0f / 128.0f);
        hgemm_av_kernel<<<dim3(d / 128, n / 128, 2), blk>>>(gS, gVp + soff, gAtth, n, d, 4, 64);
    }
    // ---- P=8 (n=512, d=4096) ----
    {
        const int n = 512, d = 4096, splitk = 8;
        const long soff = 2L * 4194304;
        hgemm_nt_kernel<<<dim3(n / 128, n / 128, 2 * splitk), blk>>>(
            gQp + soff, gKp + soff, gPart, n, d, splitk, (long)n * d, (long)n * n);
        reduce_splitk_kernel<<<(2 * n * n) / 256, blk>>>(gPart, gS, n * n, splitk);
        softmax_kernel<<<2 * n, blk>>>(gS, n, 1.0f / 64.0f);
        hgemm_av_kernel<<<dim3(d / 128, n / 128, 2), blk>>>(gS, gVp + soff, gAtth, n, d, 3, 128);
    }
    // ---- P=4 (n=2048, d=1024) ----
    {
        const int n = 2048, d = 1024;
        const long soff = 3L * 4194304;
        hgemm_nt_kernel<<<dim3(n / 128, n / 128, 2), blk>>>(
            gQp + soff, gKp + soff, gS, n, d, 1, (long)n * d, (long)n * n);
        softmax_kernel<<<2 * n, blk>>>(gS, n, 1.0f / 32.0f);
        hgemm_av_kernel<<<dim3(d / 128, n / 128, 2), blk>>>(gS, gVp + soff, gAtth, n, d, 2, 192);
    }

    // convs: l (res=xs, write f32 xs1 + half copy), f1 (half only), f2 (res=xs1, f32 out)
    hconv_kernel<<<cgrid, blk>>>(gAtth, gWlh,  bl,  xs,   gXs1,    gXs1h,  nullptr, 3, 1, 1, 1);
    hconv_kernel<<<cgrid, blk>>>(gXs1h, gWf1h, bf1, nullptr, nullptr, gFfh, nullptr, 3, 1, 1, 0);
    hconv_kernel<<<cgrid, blk>>>(gFfh,  gWf2h, bf2, gXs1, out,     nullptr, nullptr, 3, 2, 1, 1);
}

// round 7
// speedup vs baseline: 7.3698x; 1.2837x over previous
#include <cuda_runtime.h>
#include <cuda_fp16.h>
#include <math.h>
#include <stdint.h>

#define NIMG 16
#define CCH 256
#define NPIX 4096            // 64*64

// ---- scratch (static device globals; no allocation) ----
__device__ __half g_Qp[16777216];
__device__ __half g_Kp[16777216];
__device__ __half g_Vp[16777216];
__device__ float  g_S[2*2048*2048];
__device__ float  g_part[8388608];
__device__ float  g_xs1[NIMG*CCH*NPIX];
__device__ __half g_xsh [NIMG*CCH*NPIX];
__device__ __half g_atth[NIMG*CCH*NPIX];
__device__ __half g_xs1h[NIMG*CCH*NPIX];
__device__ __half g_ffh [NIMG*CCH*NPIX];
__device__ __half g_Wqh[65536], g_Wkh[65536], g_Wvh[65536];
__device__ __half g_Wlh[589824], g_Wf1h[589824], g_Wf2h[589824];   // tap-major

// ============================================================================
// helpers
// ============================================================================
__device__ __forceinline__ void mma16(float* d, const uint32_t* a, const uint32_t* b) {
    asm volatile(
        "mma.sync.aligned.m16n8k16.row.col.f32.f16.f16.f32 "
        "{%0,%1,%2,%3}, {%4,%5,%6,%7}, {%8,%9}, {%0,%1,%2,%3};"
        : "+f"(d[0]), "+f"(d[1]), "+f"(d[2]), "+f"(d[3])
        : "r"(a[0]), "r"(a[1]), "r"(a[2]), "r"(a[3]), "r"(b[0]), "r"(b[1]));
}

__device__ __forceinline__ void ldsm4(uint32_t* r, const void* p) {
    uint32_t addr = (uint32_t)__cvta_generic_to_shared(p);
    asm volatile("ldmatrix.sync.aligned.m8n8.x4.shared.b16 {%0,%1,%2,%3}, [%4];"
        : "=r"(r[0]), "=r"(r[1]), "=r"(r[2]), "=r"(r[3]) : "r"(addr));
}

__device__ __forceinline__ void ldsm4t(uint32_t* r, const void* p) {
    uint32_t addr = (uint32_t)__cvta_generic_to_shared(p);
    asm volatile("ldmatrix.sync.aligned.m8n8.x4.trans.shared.b16 {%0,%1,%2,%3}, [%4];"
        : "=r"(r[0]), "=r"(r[1]), "=r"(r[2]), "=r"(r[3]) : "r"(addr));
}

__device__ __forceinline__ uint32_t pack_h2(float a, float b) {
    __half2 h = __floats2half2_rn(a, b);
    return *(uint32_t*)&h;
}

__device__ __forceinline__ void cpa16(uint32_t dst, const void* src, unsigned sz) {
    asm volatile("cp.async.ca.shared.global [%0], [%1], 16, %2;"
                 :: "r"(dst), "l"(src), "r"(sz) : "memory");
}
__device__ __forceinline__ void cpcommit() {
    asm volatile("cp.async.commit_group;" ::: "memory");
}
template <int N>
__device__ __forceinline__ void cpwait() {
    asm volatile("cp.async.wait_group %0;" :: "n"(N) : "memory");
}

// f32 -> f16 bulk convert (exact multiples of 1024 elems)
__global__ void f2h_kernel(const float* __restrict__ src, __half* __restrict__ dst) {
    long i = ((long)blockIdx.x * 256 + threadIdx.x) * 4;
    float4 v = *(const float4*)(src + i);
    *(uint32_t*)(dst + i)     = pack_h2(v.x, v.y);
    *(uint32_t*)(dst + i + 2) = pack_h2(v.z, v.w);
}

// conv weight transpose+convert: W[oc][c][tap] f32 -> Wt2[oc][tap][c] half
__global__ void wtrans_kernel(const float* __restrict__ W, __half* __restrict__ Wt2) {
    int idx = blockIdx.x * 256 + threadIdx.x;      // 0 .. 589823
    int oc = idx / 2304, r = idx - oc * 2304;
    int tap = r >> 8, c = r & 255;
    Wt2[idx] = __float2half(W[oc * 2304 + c * 9 + tap]);
}

// scatter index into patchified buffer: scale = oc>>6
__device__ __forceinline__ long pat_index(int img, int oc, int pix) {
    int s  = oc >> 6, cc = oc & 63;
    int lp = 5 - s;
    int lo = 1 + s;
    int Pm = (1 << lp) - 1;
    int y = pix >> 6, x = pix & 63;
    int ohi = y >> lp, pi = y & Pm, owi = x >> lp, pj = x & Pm;
    int t = img & 7, b = img >> 3;
    int nn = (t << (2*lo)) + (ohi << lo) + owi;
    int dd = (cc << (2*lp)) + (pi << lp) + pj;
    return (long)s * 4194304 + (long)b * 2097152 + (long)nn * (64 << (2*lp)) + dd;
}

// ============================================================================
// hconv2: fp16 mma conv / projection, tap-major K, cp.async pipelined
//   ks==1: K=256 (weights [oc][c]); ks==3: K=2304 (weights [oc][tap][c])
//   outh_pat != null : QKV mode (scatter patchified half, bias only)
//   else: bias + (leaky) + (residual f32); optional f32 + half image outputs
// ============================================================================
__global__ void __launch_bounds__(256, 2) hconv2_kernel(
    const __half* __restrict__ in, const __half* __restrict__ Wt,
    const float* __restrict__ bias, const float* __restrict__ res,
    float* __restrict__ out, __half* __restrict__ outh_img, __half* __restrict__ outh_pat,
    int ks, int dil, int do_leaky, int addres)
{
    __shared__ __half A2[2 * 128 * 40];     // weights, double buffered
    __shared__ __half Bs[32 * 136];         // B tile (built / direct buf 1)
    __shared__ __half Strip[32 * 160];      // raw strip [c][2 rows][80] / direct buf 0

    const int tid = threadIdx.x;
    const int lane = tid & 31, wid = tid >> 5;
    const int wm = wid & 1, wn = wid >> 1;
    const int K = CCH * ks * ks;
    const int nch = K / 32;
    const int img = blockIdx.x >> 5;
    const int p0 = (blockIdx.x & 31) * 128;
    const int y0 = p0 >> 6;
    const int m0 = blockIdx.y * 128;
    const __half* inimg = in + (long)img * CCH * NPIX;

    const uint32_t sA2    = (uint32_t)__cvta_generic_to_shared(A2);
    const uint32_t sBs    = (uint32_t)__cvta_generic_to_shared(Bs);
    const uint32_t sStrip = (uint32_t)__cvta_generic_to_shared(Strip);

    // zero strip halos once (stay zero; conv path only)
    if (ks == 3 && tid < 128) {
        int c = tid >> 2, u = tid & 3, r = u >> 1, side = u & 1;
        *(uint4*)(Strip + c * 160 + r * 80 + side * 72) = make_uint4(0, 0, 0, 0);
    }

#define ISSUE(KCN, NB)                                                          \
    {                                                                           \
        const int k0n = (KCN) * 32;                                             \
        {   /* A: 128 oc x 32 k */                                              \
            int row = tid >> 1, seg = (tid & 1) * 16;                           \
            const __half* src = Wt + (long)(m0 + row) * K + k0n + seg;          \
            uint32_t dst = sA2 + (uint32_t)(((NB) * 5120 + row * 40 + seg) * 2);\
            cpa16(dst, src, 16u); cpa16(dst + 16, src + 8, 16u);                \
        }                                                                       \
        if (ks == 1) {  /* B direct: 32 k x 128 px */                           \
            int k = tid >> 3, u = tid & 7;                                      \
            const __half* src = inimg + ((long)(k0n + k) << 12) + p0 + u * 8;   \
            uint32_t dst = ((NB) ? sBs : sStrip) + (uint32_t)((k * 136 + u * 8) * 2); \
            cpa16(dst, src, 16u);                                               \
            cpa16(dst + 128, src + 64, 16u);                                    \
        } else {        /* strip: 32 ch x 2 rows x 64 px */                     \
            int tap = k0n >> 8, c0 = k0n & 255;                                 \
            int dyd = (tap / 3 - 1) * dil;                                      \
            int c = tid >> 3, u = tid & 7;                                      \
            int r = u >> 2, s = u & 3;                                          \
            int gy = y0 + r + dyd;                                              \
            unsigned ok = ((unsigned)gy < 64u) ? 16u : 0u;                      \
            int gyc = gy < 0 ? 0 : (gy > 63 ? 63 : gy);                         \
            const __half* src = inimg + ((long)(c0 + c) << 12) + (gyc << 6) + s * 8; \
            uint32_t dst = sStrip + (uint32_t)((c * 160 + r * 80 + 8 + s * 8) * 2);  \
            cpa16(dst, src, ok);                                                \
            cpa16(dst + 64, src + 32, ok);                                      \
        }                                                                       \
        cpcommit();                                                             \
    }

    float acc[4][4][4] = {};
    ISSUE(0, 0);

    for (int kc = 0; kc < nch; kc++) {
        cpwait<0>();
        __syncthreads();

        const __half* Bp;
        if (ks == 3) {
            // build shifted B tile from strip
            int tap = (kc * 32) >> 8;
            int dxd = (tap - (tap / 3) * 3 - 1) * dil;
            int c = tid >> 3, u = tid & 7, prow = u >> 2, xseg = (u & 3) * 16;
            const __half* sp = Strip + c * 160 + prow * 80 + 8 + dxd + xseg;
            uint32_t w[8];
#pragma unroll
            for (int j = 0; j < 8; j++) {
                uint32_t lo = *(const uint16_t*)(sp + 2 * j);
                uint32_t hi = *(const uint16_t*)(sp + 2 * j + 1);
                w[j] = lo | (hi << 16);
            }
            uint4* bd = (uint4*)(Bs + c * 136 + prow * 64 + xseg);
            bd[0] = make_uint4(w[0], w[1], w[2], w[3]);
            bd[1] = make_uint4(w[4], w[5], w[6], w[7]);
            __syncthreads();
            Bp = Bs;
        } else {
            Bp = (kc & 1) ? Bs : Strip;
        }

        if (kc + 1 < nch) ISSUE(kc + 1, (kc + 1) & 1);

        const __half* Ap = A2 + (kc & 1) * 5120;
#pragma unroll
        for (int kstep = 0; kstep < 2; kstep++) {
            uint32_t a[4][4], b[4][2];
            {
                const int arow = wm * 64 + ((lane >> 3) & 1) * 8 + (lane & 7);
                const int akc  = kstep * 16 + (lane >> 4) * 8;
#pragma unroll
                for (int mi = 0; mi < 4; mi++)
                    ldsm4(a[mi], Ap + (arow + mi * 16) * 40 + akc);
            }
            {
                const int brow = kstep * 16 + (lane & 7) + ((lane >> 3) & 1) * 8;
#pragma unroll
                for (int ni2 = 0; ni2 < 2; ni2++) {
                    const int bcol = wn * 32 + ni2 * 16 + ((lane >> 4) & 1) * 8;
                    uint32_t r[4];
                    ldsm4t(r, Bp + brow * 136 + bcol);
                    b[2*ni2    ][0] = r[0]; b[2*ni2    ][1] = r[1];
                    b[2*ni2 + 1][0] = r[2]; b[2*ni2 + 1][1] = r[3];
                }
            }
#pragma unroll
            for (int mi = 0; mi < 4; mi++)
#pragma unroll
                for (int ni = 0; ni < 4; ni++)
                    mma16(acc[mi][ni], a[mi], b[ni]);
        }
    }
#undef ISSUE

    const int orow = m0 + wm * 64 + (lane >> 2);
    const int ocol = p0 + wn * 32 + (lane & 3) * 2;

    if (outh_pat) {
#pragma unroll
        for (int mi = 0; mi < 4; mi++) {
            const int oca = orow + mi * 16, ocb = oca + 8;
            const float ba = bias[oca], bb = bias[ocb];
#pragma unroll
            for (int ni = 0; ni < 4; ni++) {
                const int n = ocol + ni * 8;
                long ia = pat_index(img, oca, n);
                long ib = pat_index(img, ocb, n);
                *(__half2*)(outh_pat + ia) = __floats2half2_rn(acc[mi][ni][0] + ba, acc[mi][ni][1] + ba);
                *(__half2*)(outh_pat + ib) = __floats2half2_rn(acc[mi][ni][2] + bb, acc[mi][ni][3] + bb);
            }
        }
    } else {
#pragma unroll
        for (int mi = 0; mi < 4; mi++) {
            const int oca = orow + mi * 16;
            const int ocb = oca + 8;
            const float ba = bias[oca], bb = bias[ocb];
#pragma unroll
            for (int ni = 0; ni < 4; ni++) {
                const int n = ocol + ni * 8;
                long ia = ((long)img * 256 + oca) * NPIX + n;
                long ib = ((long)img * 256 + ocb) * NPIX + n;
                float v0 = acc[mi][ni][0] + ba, v1 = acc[mi][ni][1] + ba;
                float v2 = acc[mi][ni][2] + bb, v3 = acc[mi][ni][3] + bb;
                if (do_leaky) {
                    v0 = (v0 > 0.f) ? v0 : 0.2f * v0;
                    v1 = (v1 > 0.f) ? v1 : 0.2f * v1;
                    v2 = (v2 > 0.f) ? v2 : 0.2f * v2;
                    v3 = (v3 > 0.f) ? v3 : 0.2f * v3;
                }
                if (addres) {
                    v0 += res[ia]; v1 += res[ia + 1];
                    v2 += res[ib]; v3 += res[ib + 1];
                }
                if (out) {
                    out[ia] = v0; out[ia + 1] = v1;
                    out[ib] = v2; out[ib + 1] = v3;
                }
                if (outh_img) {
                    *(__half2*)(outh_img + ia) = __floats2half2_rn(v0, v1);
                    *(__half2*)(outh_img + ib) = __floats2half2_rn(v2, v3);
                }
            }
        }
    }
}

// ============================================================================
// fp16 NT GEMM with deterministic split-K (scores), f32 out
// ============================================================================
__global__ void __launch_bounds__(256) hgemm_nt_kernel(
    const __half* __restrict__ A, const __half* __restrict__ B, float* __restrict__ C,
    int N, int K, int splitk, long sAB, long sC)
{
    __shared__ __half As[128 * 40];
    __shared__ __half Bs[128 * 40];
    const int tid = threadIdx.x;
    const int lane = tid & 31, wid = tid >> 5;
    const int wm = wid & 1, wn = wid >> 1;
    const int n0 = blockIdx.x * 128, m0 = blockIdx.y * 128;
    const int z = blockIdx.z, bat = z / splitk, ks = z - bat * splitk;
    A += (long)bat * sAB;
    B += (long)bat * sAB;
    C += (long)z * sC;
    const int kchunk = K / splitk, kbeg = ks * kchunk;
    const int wr = tid >> 1, wkh = (tid & 1) * 16;

    float acc[4][4][4] = {};
    for (int k0 = kbeg; k0 < kbeg + kchunk; k0 += 32) {
        __syncthreads();
        {
            const __half* sa = A + (long)(m0 + wr) * K + k0 + wkh;
            const __half* sb = B + (long)(n0 + wr) * K + k0 + wkh;
            *(uint4*)(As + wr * 40 + wkh)     = *(const uint4*)sa;
            *(uint4*)(As + wr * 40 + wkh + 8) = *(const uint4*)(sa + 8);
            *(uint4*)(Bs + wr * 40 + wkh)     = *(const uint4*)sb;
            *(uint4*)(Bs + wr * 40 + wkh + 8) = *(const uint4*)(sb + 8);
        }
        __syncthreads();
#pragma unroll
        for (int kstep = 0; kstep < 2; kstep++) {
            uint32_t a[4][4], b[4][2];
            {
                const int arow = wm * 64 + ((lane >> 3) & 1) * 8 + (lane & 7);
                const int akc  = kstep * 16 + (lane >> 4) * 8;
#pragma unroll
                for (int mi = 0; mi < 4; mi++)
                    ldsm4(a[mi], As + (arow + mi * 16) * 40 + akc);
            }
            {
                const int bkc = kstep * 16 + ((lane >> 3) & 1) * 8;
#pragma unroll
                for (int ni2 = 0; ni2 < 2; ni2++) {
                    const int brow = wn * 32 + ni2 * 16 + ((lane >> 4) & 1) * 8 + (lane & 7);
                    uint32_t r[4];
                    ldsm4(r, Bs + brow * 40 + bkc);
                    b[2*ni2    ][0] = r[0]; b[2*ni2    ][1] = r[1];
                    b[2*ni2 + 1][0] = r[2]; b[2*ni2 + 1][1] = r[3];
                }
            }
#pragma unroll
            for (int mi = 0; mi < 4; mi++)
#pragma unroll
                for (int ni = 0; ni < 4; ni++)
                    mma16(acc[mi][ni], a[mi], b[ni]);
        }
    }
    const int orow = m0 + wm * 64 + (lane >> 2);
    const int ocol = n0 + wn * 32 + (lane & 3) * 2;
#pragma unroll
    for (int mi = 0; mi < 4; mi++) {
        long ra = (long)(orow + mi * 16) * N;
        long rb = (long)(orow + mi * 16 + 8) * N;
#pragma unroll
        for (int ni = 0; ni < 4; ni++) {
            int n = ocol + ni * 8;
            C[ra + n] = acc[mi][ni][0]; C[ra + n + 1] = acc[mi][ni][1];
            C[rb + n] = acc[mi][ni][2]; C[rb + n + 1] = acc[mi][ni][3];
        }
    }
}

// ============================================================================
// fp16 AV GEMM (NN via trans-ldmatrix B), scatter epilogue -> half image
// ============================================================================
__global__ void __launch_bounds__(256) hgemm_av_kernel(
    const float* __restrict__ S, const __half* __restrict__ V, __half* __restrict__ out,
    int n, int d, int lp, int c0)
{
    __shared__ __half As[128 * 40];
    __shared__ __half Bs[32 * 136];
    const int tid = threadIdx.x;
    const int lane = tid & 31, wid = tid >> 5;
    const int wm = wid & 1, wn = wid >> 1;
    const int z = blockIdx.z;
    S += (long)z * n * n;
    V += (long)z * n * d;
    const int n0 = blockIdx.x * 128;
    const int m0 = blockIdx.y * 128;
    const int wr = tid >> 1, wkh = (tid & 1) * 16;
    const int bk = tid >> 3, bn0 = (tid & 7) * 16;

    float acc[4][4][4] = {};
    for (int k0 = 0; k0 < n; k0 += 32) {
        __syncthreads();
        {
            const float* sa = S + (long)(m0 + wr) * n + k0 + wkh;
            uint32_t* ad = (uint32_t*)(As + wr * 40 + wkh);
#pragma unroll
            for (int i4 = 0; i4 < 4; i4++) {
                float4 v = *(const float4*)(sa + i4 * 4);
                ad[i4*2 + 0] = pack_h2(v.x, v.y);
                ad[i4*2 + 1] = pack_h2(v.z, v.w);
            }
            const __half* sb = V + (long)(k0 + bk) * d + n0 + bn0;
            *(uint4*)(Bs + bk * 136 + bn0)     = *(const uint4*)sb;
            *(uint4*)(Bs + bk * 136 + bn0 + 8) = *(const uint4*)(sb + 8);
        }
        __syncthreads();
#pragma unroll
        for (int kstep = 0; kstep < 2; kstep++) {
            uint32_t a[4][4], b[4][2];
            {
                const int arow = wm * 64 + ((lane >> 3) & 1) * 8 + (lane & 7);
                const int akc  = kstep * 16 + (lane >> 4) * 8;
#pragma unroll
                for (int mi = 0; mi < 4; mi++)
                    ldsm4(a[mi], As + (arow + mi * 16) * 40 + akc);
            }
            {
                const int brow = kstep * 16 + (lane & 7) + ((lane >> 3) & 1) * 8;
#pragma unroll
                for (int ni2 = 0; ni2 < 2; ni2++) {
                    const int bcol = wn * 32 + ni2 * 16 + ((lane >> 4) & 1) * 8;
                    uint32_t r[4];
                    ldsm4t(r, Bs + brow * 136 + bcol);
                    b[2*ni2    ][0] = r[0]; b[2*ni2    ][1] = r[1];
                    b[2*ni2 + 1][0] = r[2]; b[2*ni2 + 1][1] = r[3];
                }
            }
#pragma unroll
            for (int mi = 0; mi < 4; mi++)
#pragma unroll
                for (int ni = 0; ni < 4; ni++)
                    mma16(acc[mi][ni], a[mi], b[ni]);
        }
    }

    const int lo = 6 - lp;
    const int orow = m0 + wm * 64 + (lane >> 2);
    const int ocol = n0 + wn * 32 + (lane & 3) * 2;
#pragma unroll
    for (int mi = 0; mi < 4; mi++) {
#pragma unroll
        for (int hf = 0; hf < 2; hf++) {
            const int m = orow + mi * 16 + hf * 8;
            const int t = m >> (2 * lo);
            const int r = m & ((1 << (2 * lo)) - 1);
            const int ohi = r >> lo, owi = r & ((1 << lo) - 1);
#pragma unroll
            for (int ni = 0; ni < 4; ni++) {
                const int col = ocol + ni * 8;
                const int cc = col >> (2 * lp);
                const int rr = col & ((1 << (2 * lp)) - 1);
                const int pi = rr >> lp, pj = rr & ((1 << lp) - 1);
                long dst = ((long)((z * 8 + t) * 256 + c0 + cc) << 12)
                         + (((ohi << lp) + pi) << 6) + (owi << lp) + pj;
                *(__half2*)(out + dst) = __floats2half2_rn(acc[mi][ni][hf*2], acc[mi][ni][hf*2 + 1]);
            }
        }
    }
}

// ============================================================================
// fp16 mma 32x32 NT split-K (P=32 scores): 2 warps, cross-warp smem reduce
// ============================================================================
__global__ void __launch_bounds__(64) hgemm32_kernel(
    const __half* __restrict__ A, const __half* __restrict__ B, float* __restrict__ C,
    int K, int splitk)
{
    __shared__ __half Qs[32 * 136];
    __shared__ __half Ks[32 * 136];
    __shared__ float buf[32][33];
    const int tid = threadIdx.x;
    const int lane = tid & 31, wrp = tid >> 5;
    const int z = blockIdx.z, bat = z / splitk, ks = z - bat * splitk;
    A += (long)bat * 32 * K;
    B += (long)bat * 32 * K;
    const int kchunk = K / splitk, kbeg = ks * kchunk;

    float acc[2][4][4] = {};
    for (int k0 = kbeg; k0 < kbeg + kchunk; k0 += 128) {
        __syncthreads();
#pragma unroll
        for (int i = 0; i < 8; i++) {
            int u = i * 64 + tid;
            int row = u >> 4, seg = (u & 15) * 8;
            *(uint4*)(Qs + row * 136 + seg) = *(const uint4*)(A + (long)row * K + k0 + seg);
            *(uint4*)(Ks + row * 136 + seg) = *(const uint4*)(B + (long)row * K + k0 + seg);
        }
        __syncthreads();
        for (int s = wrp; s < 8; s += 2) {
            const int kc = s * 16;
            uint32_t a[2][4], b[4][2];
            {
                const int arow = ((lane >> 3) & 1) * 8 + (lane & 7);
                const int akc  = kc + (lane >> 4) * 8;
                ldsm4(a[0], Qs + arow * 136 + akc);
                ldsm4(a[1], Qs + (arow + 16) * 136 + akc);
            }
            {
                const int bkc = kc + ((lane >> 3) & 1) * 8;
#pragma unroll
                for (int ni2 = 0; ni2 < 2; ni2++) {
                    const int brow = ni2 * 16 + ((lane >> 4) & 1) * 8 + (lane & 7);
                    uint32_t r[4];
                    ldsm4(r, Ks + brow * 136 + bkc);
                    b[2*ni2    ][0] = r[0]; b[2*ni2    ][1] = r[1];
                    b[2*ni2 + 1][0] = r[2]; b[2*ni2 + 1][1] = r[3];
                }
            }
#pragma unroll
            for (int mi = 0; mi < 2; mi++)
#pragma unroll
                for (int ni = 0; ni < 4; ni++)
                    mma16(acc[mi][ni], a[mi], b[ni]);
        }
    }

    const int rr = lane >> 2, cc = (lane & 3) * 2;
    if (wrp == 0) {
#pragma unroll
        for (int mi = 0; mi < 2; mi++)
#pragma unroll
            for (int ni = 0; ni < 4; ni++) {
                buf[mi*16 + rr    ][ni*8 + cc]     = acc[mi][ni][0];
                buf[mi*16 + rr    ][ni*8 + cc + 1] = acc[mi][ni][1];
                buf[mi*16 + rr + 8][ni*8 + cc]     = acc[mi][ni][2];
                buf[mi*16 + rr + 8][ni*8 + cc + 1] = acc[mi][ni][3];
            }
    }
    __syncthreads();
    if (wrp == 1) {
#pragma unroll
        for (int mi = 0; mi < 2; mi++)
#pragma unroll
            for (int ni = 0; ni < 4; ni++) {
                buf[mi*16 + rr    ][ni*8 + cc]     += acc[mi][ni][0];
                buf[mi*16 + rr    ][ni*8 + cc + 1] += acc[mi][ni][1];
                buf[mi*16 + rr + 8][ni*8 + cc]     += acc[mi][ni][2];
                buf[mi*16 + rr + 8][ni*8 + cc + 1] += acc[mi][ni][3];
            }
    }
    __syncthreads();
    float* Cz = C + (long)z * 1024;
    for (int i = tid; i < 1024; i += 64)
        Cz[i] = buf[i >> 5][i & 31];
}

__global__ void reduce_splitk_kernel(const float* __restrict__ part, float* __restrict__ S,
                                     int per, int splitk)
{
    long idx = (long)blockIdx.x * 256 + threadIdx.x;
    int b = (int)(idx / per);
    int r = (int)(idx - (long)b * per);
    float s = 0.f;
    for (int ks = 0; ks < splitk; ks++)
        s += part[(long)(b * splitk + ks) * per + r];
    S[idx] = s;
}

// ===================== SIMT AV for P=32 (M=32, half V), half out ==================
__global__ void __launch_bounds__(256) gemm_av32_kernel(
    const float* __restrict__ A, const __half* __restrict__ B, __half* __restrict__ out,
    int n, int d, int lp, int c0)
{
    const int z = blockIdx.z;
    A += (long)z * n * n;
    B += (long)z * n * d;
    const int m0 = blockIdx.y * 64, n0 = blockIdx.x * 64;
    __shared__ __align__(16) float As[16][68];
    __shared__ __align__(16) float Bs[16][64];
    const int tid = threadIdx.x;
    const int tx = tid & 15, ty = tid >> 4;
    float acc[4][4] = {};
    for (int k0 = 0; k0 < n; k0 += 16) {
#pragma unroll
        for (int it = 0; it < 4; it++) {
            int id = tid + it * 256;
            int m = id >> 4, kk = id & 15;
            As[kk][m] = (m0 + m < n) ? A[(long)(m0 + m) * n + k0 + kk] : 0.f;
        }
#pragma unroll
        for (int it = 0; it < 4; it++) {
            int id = tid + it * 256;
            int kk = id >> 6, nnn = id & 63;
            Bs[kk][nnn] = __half2float(B[(long)(k0 + kk) * d + n0 + nnn]);
        }
        __syncthreads();
#pragma unroll
        for (int kk = 0; kk < 16; kk++) {
            float4 a4 = *(const float4*)&As[kk][ty * 4];
            float4 b4 = *(const float4*)&Bs[kk][tx * 4];
            float ar[4] = {a4.x, a4.y, a4.z, a4.w};
            float br[4] = {b4.x, b4.y, b4.z, b4.w};
#pragma unroll
            for (int i = 0; i < 4; i++)
#pragma unroll
                for (int j = 0; j < 4; j++)
                    acc[i][j] += ar[i] * br[j];
        }
        __syncthreads();
    }
    const int lo = 6 - lp, o = 1 << lo, P = 1 << lp;
#pragma unroll
    for (int i = 0; i < 4; i++) {
        int m = m0 + ty * 4 + i;
        if (m >= n) continue;
        int t = m >> (2 * lo);
        int r = m & ((1 << (2 * lo)) - 1);
        int ohi = r >> lo, owi = r & (o - 1);
        int col = n0 + tx * 4;
        int cc = col >> (2 * lp);
        int rr = col & (P * P - 1);
        int pi = rr >> lp, pj = rr & (P - 1);
        long dst = ((long)((z * 8 + t) * 256 + c0 + cc) << 12)
                 + (((ohi << lp) + pi) << 6) + (owi << lp) + pj;
        *(__half2*)(out + dst)     = __floats2half2_rn(acc[i][0], acc[i][1]);
        *(__half2*)(out + dst + 2) = __floats2half2_rn(acc[i][2], acc[i][3]);
    }
}

// ===================== softmax (row-wise, scale folded in) ========================
__global__ void softmax_kernel(float* __restrict__ S, int n, float scale)
{
    __shared__ float buf[2048];
    __shared__ float red[256];
    const long row = blockIdx.x;
    float* p = S + row * (long)n;
    const int tid = threadIdx.x;
    float m = -1e30f;
    for (int i = tid; i < n; i += 256) { float v = p[i] * scale; buf[i] = v; m = fmaxf(m, v); }
    red[tid] = m; __syncthreads();
    for (int s = 128; s > 0; s >>= 1) { if (tid < s) red[tid] = fmaxf(red[tid], red[tid + s]); __syncthreads(); }
    m = red[0]; __syncthreads();
    float sum = 0.f;
    for (int i = tid; i < n; i += 256) { float e = expf(buf[i] - m); buf[i] = e; sum += e; }
    red[tid] = sum; __syncthreads();
    for (int s = 128; s > 0; s >>= 1) { if (tid < s) red[tid] += red[tid + s]; __syncthreads(); }
    float inv = 1.f / red[0];
    for (int i = tid; i < n; i += 256) p[i] = buf[i] * inv;
}

// ===================== launcher ===================================================
extern "C" void kernel_launch(void* const* d_in, const int* in_sizes, int n_in,
                              void* d_out, int out_size)
{
    const float* xs  = (const float*)d_in[0];
    const float* Wq  = (const float*)d_in[2];
    const float* bq  = (const float*)d_in[3];
    const float* Wk  = (const float*)d_in[4];
    const float* bk  = (const float*)d_in[5];
    const float* Wv  = (const float*)d_in[6];
    const float* bv  = (const float*)d_in[7];
    const float* Wl  = (const float*)d_in[8];
    const float* bl  = (const float*)d_in[9];
    const float* Wf1 = (const float*)d_in[10];
    const float* bf1 = (const float*)d_in[11];
    const float* Wf2 = (const float*)d_in[12];
    const float* bf2 = (const float*)d_in[13];
    float* out = (float*)d_out;

    __half *gQp, *gKp, *gVp, *gXsh, *gAtth, *gXs1h, *gFfh;
    __half *gWqh, *gWkh, *gWvh, *gWlh, *gWf1h, *gWf2h;
    float *gS, *gPart, *gXs1;
    cudaGetSymbolAddress((void**)&gQp,   g_Qp);
    cudaGetSymbolAddress((void**)&gKp,   g_Kp);
    cudaGetSymbolAddress((void**)&gVp,   g_Vp);
    cudaGetSymbolAddress((void**)&gS,    g_S);
    cudaGetSymbolAddress((void**)&gPart, g_part);
    cudaGetSymbolAddress((void**)&gXs1,  g_xs1);
    cudaGetSymbolAddress((void**)&gXsh,  g_xsh);
    cudaGetSymbolAddress((void**)&gAtth, g_atth);
    cudaGetSymbolAddress((void**)&gXs1h, g_xs1h);
    cudaGetSymbolAddress((void**)&gFfh,  g_ffh);
    cudaGetSymbolAddress((void**)&gWqh,  g_Wqh);
    cudaGetSymbolAddress((void**)&gWkh,  g_Wkh);
    cudaGetSymbolAddress((void**)&gWvh,  g_Wvh);
    cudaGetSymbolAddress((void**)&gWlh,  g_Wlh);
    cudaGetSymbolAddress((void**)&gWf1h, g_Wf1h);
    cudaGetSymbolAddress((void**)&gWf2h, g_Wf2h);

    dim3 blk(256);
    dim3 cgrid(NIMG * 32, 2);

    // pre-convert inputs + weights (convs: transpose to tap-major)
    f2h_kernel<<<16384, blk>>>(xs,  gXsh);
    f2h_kernel<<<64,    blk>>>(Wq,  gWqh);
    f2h_kernel<<<64,    blk>>>(Wk,  gWkh);
    f2h_kernel<<<64,    blk>>>(Wv,  gWvh);
    wtrans_kernel<<<2304, blk>>>(Wl,  gWlh);
    wtrans_kernel<<<2304, blk>>>(Wf1, gWf1h);
    wtrans_kernel<<<2304, blk>>>(Wf2, gWf2h);

    // QKV projections -> patchified half buffers (bias fused)
    hconv2_kernel<<<cgrid, blk>>>(gXsh, gWqh, bq, nullptr, nullptr, nullptr, gQp, 1, 1, 0, 0);
    hconv2_kernel<<<cgrid, blk>>>(gXsh, gWkh, bk, nullptr, nullptr, nullptr, gKp, 1, 1, 0, 0);
    hconv2_kernel<<<cgrid, blk>>>(gXsh, gWvh, bv, nullptr, nullptr, nullptr, gVp, 1, 1, 0, 0);

    // ---- P=32 (n=32, d=65536) ----
    {
        const int n = 32, d = 65536, splitk = 256;
        hgemm32_kernel<<<dim3(1, 1, 2 * splitk), 64>>>(gQp, gKp, gPart, d, splitk);
        reduce_splitk_kernel<<<(2 * n * n) / 256, blk>>>(gPart, gS, n * n, splitk);
        softmax_kernel<<<2 * n, blk>>>(gS, n, 1.0f / 256.0f);
        gemm_av32_kernel<<<dim3(d / 64, 1, 2), blk>>>(gS, gVp, gAtth, n, d, 5, 0);
    }
    // ---- P=16 (n=128, d=16384) ----
    {
        const int n = 128, d = 16384, splitk = 64;
        const long soff = 4194304;
        hgemm_nt_kernel<<<dim3(1, 1, 2 * splitk), blk>>>(
            gQp + soff, gKp + soff, gPart, n, d, splitk, (long)n * d, (long)n * n);
        reduce_splitk_kernel<<<(2 * n * n) / 256, blk>>>(gPart, gS, n * n, splitk);
        softmax_kernel<<<2 * n, blk>>>(gS, n, 1.0f / 128.0f);
        hgemm_av_kernel<<<dim3(d / 128, n / 128, 2), blk>>>(gS, gVp + soff, gAtth, n, d, 4, 64);
    }
    // ---- P=8 (n=512, d=4096) ----
    {
        const int n = 512, d = 4096, splitk = 8;
        const long soff = 2L * 4194304;
        hgemm_nt_kernel<<<dim3(n / 128, n / 128, 2 * splitk), blk>>>(
            gQp + soff, gKp + soff, gPart, n, d, splitk, (long)n * d, (long)n * n);
        reduce_splitk_kernel<<<(2 * n * n) / 256, blk>>>(gPart, gS, n * n, splitk);
        softmax_kernel<<<2 * n, blk>>>(gS, n, 1.0f / 64.0f);
        hgemm_av_kernel<<<dim3(d / 128, n / 128, 2), blk>>>(gS, gVp + soff, gAtth, n, d, 3, 128);
    }
    // ---- P=4 (n=2048, d=1024) ----
    {
        const int n = 2048, d = 1024;
        const long soff = 3L * 4194304;
        hgemm_nt_kernel<<<dim3(n / 128, n / 128, 2), blk>>>(
            gQp + soff, gKp + soff, gS, n, d, 1, (long)n * d, (long)n * n);
        softmax_kernel<<<2 * n, blk>>>(gS, n, 1.0f / 32.0f);
        hgemm_av_kernel<<<dim3(d / 128, n / 128, 2), blk>>>(gS, gVp + soff, gAtth, n, d, 2, 192);
    }

    // convs (tap-major weights)
    hconv2_kernel<<<cgrid, blk>>>(gAtth, gWlh,  bl,  xs,      gXs1,    gXs1h,   nullptr, 3, 1, 1, 1);
    hconv2_kernel<<<cgrid, blk>>>(gXs1h, gWf1h, bf1, nullptr, nullptr, gFfh,    nullptr, 3, 1, 1, 0);
    hconv2_kernel<<<cgrid, blk>>>(gFfh,  gWf2h, bf2, gXs1,    out,     nullptr, nullptr, 3, 2, 1, 1);
}